// round 2
// baseline (speedup 1.0000x reference)
#include <cuda_runtime.h>
#include <math.h>

#define B_ 32
#define T_ 128
#define H_ 1024
#define E_ 1024
#define V_ 32000
#define M_ (B_*T_)   // 4096

// Scratch (allocation-free): xW buffer reused for both layers, plus per-layer
// hidden-state sequences (seq[l][(b*T + t)*H + j] = h_t of layer l).
__device__ float g_xw[M_ * H_];
__device__ float g_seq0[M_ * H_];
__device__ float g_seq1[M_ * H_];

// ---------------------------------------------------------------------------
// SGEMM (NT): C[m,n] = sum_k A[m,k] * Bw[n,k] + bias[n]
// A rows optionally gathered: if ids != nullptr, row m = table[ids[m]].
// Tiles: BM=128, BN=128, BK=16, 256 threads, 8x8 register tile per thread.
// Requires M % 128 == 0, N % 128 == 0, K % 16 == 0 (holds for all our shapes).
// ---------------------------------------------------------------------------
__global__ __launch_bounds__(256) void sgemm_nt(
    const float* __restrict__ A, const float* __restrict__ Bw,
    const float* __restrict__ bias, float* __restrict__ C,
    int N, int K,
    const int* __restrict__ ids, const float* __restrict__ table)
{
    __shared__ float As[16][132];
    __shared__ float Bs[16][132];

    const int tid = threadIdx.x;
    const int m0 = blockIdx.x * 128;   // m-tiles fast -> W tile reuse in L2
    const int n0 = blockIdx.y * 128;

    const int tn = tid & 15;           // 0..15 (n direction)
    const int tm = tid >> 4;           // 0..15 (m direction)

    // Tile-load mapping: each thread loads 2 float4 per operand tile.
    const int lrow = tid >> 2;         // 0..63
    const int lq   = (tid & 3) * 4;    // k offset within BK: 0,4,8,12

    const float* a0;
    const float* a1;
    if (ids) {
        a0 = table + (size_t)ids[m0 + lrow]      * K;
        a1 = table + (size_t)ids[m0 + lrow + 64] * K;
    } else {
        a0 = A + (size_t)(m0 + lrow)      * K;
        a1 = A + (size_t)(m0 + lrow + 64) * K;
    }
    const float* b0 = Bw + (size_t)(n0 + lrow)      * K;
    const float* b1 = Bw + (size_t)(n0 + lrow + 64) * K;

    float acc[8][8] = {};

    for (int k0 = 0; k0 < K; k0 += 16) {
        float4 av0 = *(const float4*)(a0 + k0 + lq);
        float4 av1 = *(const float4*)(a1 + k0 + lq);
        float4 bv0 = *(const float4*)(b0 + k0 + lq);
        float4 bv1 = *(const float4*)(b1 + k0 + lq);

        As[lq+0][lrow] = av0.x; As[lq+1][lrow] = av0.y;
        As[lq+2][lrow] = av0.z; As[lq+3][lrow] = av0.w;
        As[lq+0][lrow+64] = av1.x; As[lq+1][lrow+64] = av1.y;
        As[lq+2][lrow+64] = av1.z; As[lq+3][lrow+64] = av1.w;

        Bs[lq+0][lrow] = bv0.x; Bs[lq+1][lrow] = bv0.y;
        Bs[lq+2][lrow] = bv0.z; Bs[lq+3][lrow] = bv0.w;
        Bs[lq+0][lrow+64] = bv1.x; Bs[lq+1][lrow+64] = bv1.y;
        Bs[lq+2][lrow+64] = bv1.z; Bs[lq+3][lrow+64] = bv1.w;

        __syncthreads();

        #pragma unroll
        for (int kk = 0; kk < 16; kk++) {
            float am[8], bn[8];
            #pragma unroll
            for (int i = 0; i < 8; i++) am[i] = As[kk][tm * 8 + i];
            #pragma unroll
            for (int j = 0; j < 8; j++) bn[j] = Bs[kk][tn * 8 + j];
            #pragma unroll
            for (int i = 0; i < 8; i++)
                #pragma unroll
                for (int j = 0; j < 8; j++)
                    acc[i][j] += am[i] * bn[j];
        }
        __syncthreads();
    }

    #pragma unroll
    for (int i = 0; i < 8; i++) {
        float* crow = C + (size_t)(m0 + tm * 8 + i) * N + n0 + tn * 8;
        #pragma unroll
        for (int j = 0; j < 8; j += 4) {
            float4 v;
            v.x = acc[i][j + 0] + bias[n0 + tn * 8 + j + 0];
            v.y = acc[i][j + 1] + bias[n0 + tn * 8 + j + 1];
            v.z = acc[i][j + 2] + bias[n0 + tn * 8 + j + 2];
            v.w = acc[i][j + 3] + bias[n0 + tn * 8 + j + 3];
            *(float4*)(crow + j) = v;
        }
    }
}

// ---------------------------------------------------------------------------
// One RNN timestep: seq[:, t, :] = tanh(xw[:, t, :] + hprev @ Whh^T + bhh)
// Grid: 128 blocks (8 output columns each), 256 threads.
// Thread (warp w, lane b): output (b, j = blk*8 + w).
// hprev[b, k] = hprev[b*hstride + k]  (hstride = H for init hidden,
//                                      T*H for seq rows of step t-1).
// ---------------------------------------------------------------------------
__global__ __launch_bounds__(256) void rnn_step(
    const float* __restrict__ xw,    // [B*T, H]
    const float* __restrict__ Whh,   // [H, H]
    const float* __restrict__ bhh,   // [H]
    const float* __restrict__ hprev, int hstride,
    float* __restrict__ seq,         // [B*T, H]
    int t)
{
    __shared__ float sh[32][129];    // h chunk: 32 b x 128 k, conflict-free
    const int tid  = threadIdx.x;
    const int lane = tid & 31;       // = b
    const int warp = tid >> 5;
    const int j = blockIdx.x * 8 + warp;

    const float* wrow = Whh + (size_t)j * H_;
    float acc = 0.f;

    for (int kc = 0; kc < H_; kc += 128) {
        #pragma unroll
        for (int i = 0; i < 16; i++) {
            int flat = tid + i * 256;
            int b = flat >> 7, k = flat & 127;
            sh[b][k] = hprev[(size_t)b * hstride + kc + k];
        }
        __syncthreads();
        #pragma unroll
        for (int kk = 0; kk < 128; kk += 4) {
            float4 w = *(const float4*)(wrow + kc + kk);
            acc += sh[lane][kk + 0] * w.x + sh[lane][kk + 1] * w.y
                 + sh[lane][kk + 2] * w.z + sh[lane][kk + 3] * w.w;
        }
        __syncthreads();
    }

    const int b = lane;
    float pre = acc + xw[((size_t)b * T_ + t) * H_ + j] + bhh[j];
    seq[((size_t)b * T_ + t) * H_ + j] = tanhf(pre);
}

// rnn_hidden[l][b][j] = final h of layer l = seq_l[(b*T + T-1)*H + j]
__global__ void copy_hidden(const float* __restrict__ seq0,
                            const float* __restrict__ seq1,
                            float* __restrict__ out)
{
    int idx = blockIdx.x * 256 + threadIdx.x;          // 0..65535
    int l = idx >> 15;                                 // / (B*H)
    int rem = idx & 32767;
    int b = rem >> 10, j = rem & 1023;
    const float* s = l ? seq1 : seq0;
    out[idx] = s[((size_t)b * T_ + (T_ - 1)) * H_ + j];
}

// last_output[b][v] = output_prob[(b*T + T-1)*V + v]
__global__ void copy_last(const float* __restrict__ outprob,
                          float* __restrict__ last)
{
    int idx = blockIdx.x * 256 + threadIdx.x;          // 0..1023999
    int b = idx / V_, v = idx - b * V_;
    last[idx] = outprob[((size_t)b * T_ + (T_ - 1)) * V_ + v];
}

extern "C" void kernel_launch(void* const* d_in, const int* in_sizes, int n_in,
                              void* d_out, int out_size)
{
    const int*   ids    = (const int*)  d_in[0];   // input_x [B,T] int32
    const float* hidden = (const float*)d_in[1];   // [L,B,H] (init h)
    const float* emb    = (const float*)d_in[2];   // [V,E]
    const float* Wih0   = (const float*)d_in[3];   // [H,E]
    const float* Whh0   = (const float*)d_in[4];   // [H,H]
    const float* bih0   = (const float*)d_in[5];
    const float* bhh0   = (const float*)d_in[6];
    const float* Wih1   = (const float*)d_in[7];   // [H,H]
    const float* Whh1   = (const float*)d_in[8];
    const float* bih1   = (const float*)d_in[9];
    const float* bhh1   = (const float*)d_in[10];
    const float* Wout   = (const float*)d_in[11];  // [V,H]
    const float* bout   = (const float*)d_in[12];  // [V]

    float* out      = (float*)d_out;
    float* outprob  = out;                                   // [B*T, V]
    float* rnnhid   = out + (size_t)M_ * V_;                 // [2, B, H]
    float* lastout  = rnnhid + 2 * B_ * H_;                  // [B, V]

    float *xw, *seq0, *seq1;
    cudaGetSymbolAddress((void**)&xw,   g_xw);
    cudaGetSymbolAddress((void**)&seq0, g_seq0);
    cudaGetSymbolAddress((void**)&seq1, g_seq1);

    dim3 gproj(M_ / 128, H_ / 128);   // (32, 8)

    // Layer 0: xW = emb[ids] @ Wih0^T + bih0 (fused gather)
    sgemm_nt<<<gproj, 256>>>(nullptr, Wih0, bih0, xw, H_, E_, ids, emb);
    for (int t = 0; t < T_; t++) {
        const float* hp = (t == 0) ? hidden : (seq0 + (size_t)(t - 1) * H_);
        int hs = (t == 0) ? H_ : (T_ * H_);
        rnn_step<<<128, 256>>>(xw, Whh0, bhh0, hp, hs, seq0, t);
    }

    // Layer 1: xW = seq0 @ Wih1^T + bih1
    sgemm_nt<<<gproj, 256>>>(seq0, Wih1, bih1, xw, H_, H_, nullptr, nullptr);
    for (int t = 0; t < T_; t++) {
        const float* hp = (t == 0) ? (hidden + B_ * H_)
                                   : (seq1 + (size_t)(t - 1) * H_);
        int hs = (t == 0) ? H_ : (T_ * H_);
        rnn_step<<<128, 256>>>(xw, Whh1, bhh1, hp, hs, seq1, t);
    }

    // rnn_hidden output
    copy_hidden<<<(2 * B_ * H_) / 256, 256>>>(seq0, seq1, rnnhid);

    // Output projection: [4096,1024] @ [1024,32000]^T(NT) + b_out
    dim3 gout(M_ / 128, V_ / 128);    // (32, 250), m fast for W-tile L2 reuse
    sgemm_nt<<<gout, 256>>>(seq1, Wout, bout, outprob, V_, H_, nullptr, nullptr);

    // last_output = rows t = T-1 of output_prob
    copy_last<<<(B_ * V_) / 256, 256>>>(outprob, lastout);
}

// round 3
// speedup vs baseline: 1.9411x; 1.9411x over previous
#include <cuda_runtime.h>
#include <math.h>

#define B_ 32
#define T_ 128
#define H_ 1024
#define E_ 1024
#define V_ 32000
#define M_ (B_*T_)   // 4096
#define NBLK 128
#define WPAD 1028    // padded row stride (floats): conflict-free, 16B aligned

// Scratch (allocation-free)
__device__ float g_xw[M_ * H_];
__device__ float g_seq0[M_ * H_];
__device__ float g_seq1[M_ * H_];
__device__ unsigned g_flags[NBLK];   // monotonic across launches/replays

// ---------------------------------------------------------------------------
// packed fp32x2 FMA (PTX-only; 2x fp32 FMA throughput)
// ---------------------------------------------------------------------------
__device__ __forceinline__ unsigned long long ffma2(
    unsigned long long a, unsigned long long b, unsigned long long c)
{
    unsigned long long d;
    asm("fma.rn.f32x2 %0, %1, %2, %3;" : "=l"(d) : "l"(a), "l"(b), "l"(c));
    return d;
}

// ---------------------------------------------------------------------------
// SGEMM (NT): C[m,n] = sum_k A[m,k] * Bw[n,k] + bias[n]
// Optional row gather via ids/table. BM=BN=128, BK=16, 256 thr, 8x8 rtile.
// ---------------------------------------------------------------------------
__global__ __launch_bounds__(256) void sgemm_nt(
    const float* __restrict__ A, const float* __restrict__ Bw,
    const float* __restrict__ bias, float* __restrict__ C,
    int N, int K,
    const int* __restrict__ ids, const float* __restrict__ table)
{
    __shared__ float As[16][132];
    __shared__ float Bs[16][132];

    const int tid = threadIdx.x;
    const int m0 = blockIdx.x * 128;
    const int n0 = blockIdx.y * 128;

    const int tn = tid & 15;
    const int tm = tid >> 4;

    const int lrow = tid >> 2;
    const int lq   = (tid & 3) * 4;

    const float* a0;
    const float* a1;
    if (ids) {
        a0 = table + (size_t)ids[m0 + lrow]      * K;
        a1 = table + (size_t)ids[m0 + lrow + 64] * K;
    } else {
        a0 = A + (size_t)(m0 + lrow)      * K;
        a1 = A + (size_t)(m0 + lrow + 64) * K;
    }
    const float* b0 = Bw + (size_t)(n0 + lrow)      * K;
    const float* b1 = Bw + (size_t)(n0 + lrow + 64) * K;

    float acc[8][8] = {};

    for (int k0 = 0; k0 < K; k0 += 16) {
        float4 av0 = *(const float4*)(a0 + k0 + lq);
        float4 av1 = *(const float4*)(a1 + k0 + lq);
        float4 bv0 = *(const float4*)(b0 + k0 + lq);
        float4 bv1 = *(const float4*)(b1 + k0 + lq);

        As[lq+0][lrow] = av0.x; As[lq+1][lrow] = av0.y;
        As[lq+2][lrow] = av0.z; As[lq+3][lrow] = av0.w;
        As[lq+0][lrow+64] = av1.x; As[lq+1][lrow+64] = av1.y;
        As[lq+2][lrow+64] = av1.z; As[lq+3][lrow+64] = av1.w;

        Bs[lq+0][lrow] = bv0.x; Bs[lq+1][lrow] = bv0.y;
        Bs[lq+2][lrow] = bv0.z; Bs[lq+3][lrow] = bv0.w;
        Bs[lq+0][lrow+64] = bv1.x; Bs[lq+1][lrow+64] = bv1.y;
        Bs[lq+2][lrow+64] = bv1.z; Bs[lq+3][lrow+64] = bv1.w;

        __syncthreads();

        #pragma unroll
        for (int kk = 0; kk < 16; kk++) {
            float am[8], bn[8];
            #pragma unroll
            for (int i = 0; i < 8; i++) am[i] = As[kk][tm * 8 + i];
            #pragma unroll
            for (int j = 0; j < 8; j++) bn[j] = Bs[kk][tn * 8 + j];
            #pragma unroll
            for (int i = 0; i < 8; i++)
                #pragma unroll
                for (int j = 0; j < 8; j++)
                    acc[i][j] += am[i] * bn[j];
        }
        __syncthreads();
    }

    #pragma unroll
    for (int i = 0; i < 8; i++) {
        float* crow = C + (size_t)(m0 + tm * 8 + i) * N + n0 + tn * 8;
        #pragma unroll
        for (int j = 0; j < 8; j += 4) {
            float4 v;
            v.x = acc[i][j + 0] + bias[n0 + tn * 8 + j + 0];
            v.y = acc[i][j + 1] + bias[n0 + tn * 8 + j + 1];
            v.z = acc[i][j + 2] + bias[n0 + tn * 8 + j + 2];
            v.w = acc[i][j + 3] + bias[n0 + tn * 8 + j + 3];
            *(float4*)(crow + j) = v;
        }
    }
}

// ---------------------------------------------------------------------------
// Persistent RNN scan: one launch runs all T timesteps of one layer.
// Grid: 128 CTAs (all co-resident; software grid barrier between steps).
// CTA bid owns output columns j in [bid*8, bid*8+8); W rows cached in smem.
// Thread map: warp w (0..7), lane: bq=lane>>3, jloc=lane&7;
//             b = w*4+bq, j = bid*8+jloc  -> one output (b,j) per thread.
// ---------------------------------------------------------------------------
__global__ __launch_bounds__(256, 1) void rnn_scan(
    const float* __restrict__ xw,    // [B*T, H] (b-major, t inside)
    const float* __restrict__ Whh,   // [H, H]
    const float* __restrict__ bhh,   // [H]
    const float* __restrict__ h0,    // [B, H] initial hidden
    float* __restrict__ seq)         // [B*T, H] output states
{
    extern __shared__ float smem[];
    float* Ws = smem;                 // [8][WPAD]
    float* sh = smem + 8 * WPAD;      // [32][WPAD]

    const int tid  = threadIdx.x;
    const int bid  = blockIdx.x;
    const int w    = tid >> 5;
    const int lane = tid & 31;
    const int bq   = lane >> 3;
    const int jloc = lane & 7;
    const int b    = w * 4 + bq;
    const int j    = bid * 8 + jloc;

    // Cache this CTA's 8 W_hh rows in smem (once).
    {
        const float4* W4 = (const float4*)(Whh + (size_t)bid * 8 * H_);
        #pragma unroll
        for (int i = 0; i < 8; i++) {
            int q = i * 256 + tid;          // 0..2047
            int row = q >> 8, kv = q & 255;
            float4 v = W4[row * 256 + kv];
            *(float4*)(Ws + row * WPAD + kv * 4) = v;
        }
    }

    // Uniform monotonic barrier base (all flags equal at kernel entry).
    __shared__ unsigned sbase;
    if (tid == 0) sbase = g_flags[bid];
    __syncthreads();
    const unsigned base = sbase;

    const float bj = bhh[j];

    for (int t = 0; t < T_; t++) {
        // --- wait for all CTAs to have finished step t-1 ---
        if (t > 0) {
            if (tid < 32) {
                unsigned need = base + (unsigned)t;
                #pragma unroll
                for (int f = lane; f < NBLK; f += 32) {
                    while (*((volatile unsigned*)&g_flags[f]) < need) { }
                }
            }
            __syncthreads();
        }

        // --- stage h_{t-1} (32 x 1024) into smem, L2-coherent loads ---
        if (t == 0) {
            #pragma unroll
            for (int i = 0; i < 32; i++) {
                int q = i * 256 + tid;      // 0..8191
                int bb = q >> 8, kv = q & 255;
                float4 v = __ldcg((const float4*)(h0 + (size_t)bb * H_) + kv);
                *(float4*)(sh + bb * WPAD + kv * 4) = v;
            }
        } else {
            #pragma unroll
            for (int i = 0; i < 32; i++) {
                int q = i * 256 + tid;
                int bb = q >> 8, kv = q & 255;
                float4 v = __ldcg(
                    (const float4*)(seq + ((size_t)bb * T_ + (t - 1)) * H_) + kv);
                *(float4*)(sh + bb * WPAD + kv * 4) = v;
            }
        }
        __syncthreads();

        // --- dot(h[b,:], W[j,:]) with packed f32x2 FMAs ---
        const ulonglong2* h2 = (const ulonglong2*)(sh + b * WPAD);
        const ulonglong2* w2 = (const ulonglong2*)(Ws + jloc * WPAD);
        unsigned long long a0 = 0ull, a1 = 0ull, a2 = 0ull, a3 = 0ull;
        #pragma unroll 8
        for (int kk = 0; kk < 256; kk += 2) {   // 256 x 16B = 1024 floats
            ulonglong2 hv0 = h2[kk],     wv0 = w2[kk];
            ulonglong2 hv1 = h2[kk + 1], wv1 = w2[kk + 1];
            a0 = ffma2(hv0.x, wv0.x, a0);
            a1 = ffma2(hv0.y, wv0.y, a1);
            a2 = ffma2(hv1.x, wv1.x, a2);
            a3 = ffma2(hv1.y, wv1.y, a3);
        }
        float2 s0 = *(float2*)&a0, s1 = *(float2*)&a1;
        float2 s2 = *(float2*)&a2, s3 = *(float2*)&a3;
        float sum = ((s0.x + s0.y) + (s1.x + s1.y))
                  + ((s2.x + s2.y) + (s3.x + s3.y));

        float pre = sum + xw[((size_t)b * T_ + t) * H_ + j] + bj;
        seq[((size_t)b * T_ + t) * H_ + j] = tanhf(pre);

        // --- publish step t ---
        __threadfence();
        __syncthreads();
        if (tid == 0) atomicExch(&g_flags[bid], base + (unsigned)t + 1u);
    }
}

// rnn_hidden[l][b][j] = seq_l[(b*T + T-1)*H + j]
__global__ void copy_hidden(const float* __restrict__ seq0,
                            const float* __restrict__ seq1,
                            float* __restrict__ out)
{
    int idx = blockIdx.x * 256 + threadIdx.x;
    int l = idx >> 15;
    int rem = idx & 32767;
    int b = rem >> 10, j = rem & 1023;
    const float* s = l ? seq1 : seq0;
    out[idx] = s[((size_t)b * T_ + (T_ - 1)) * H_ + j];
}

// last_output[b][v] = output_prob[(b*T + T-1)*V + v]
__global__ void copy_last(const float* __restrict__ outprob,
                          float* __restrict__ last)
{
    int idx = blockIdx.x * 256 + threadIdx.x;
    int b = idx / V_, v = idx - b * V_;
    last[idx] = outprob[((size_t)b * T_ + (T_ - 1)) * V_ + v];
}

extern "C" void kernel_launch(void* const* d_in, const int* in_sizes, int n_in,
                              void* d_out, int out_size)
{
    const int*   ids    = (const int*)  d_in[0];
    const float* hidden = (const float*)d_in[1];
    const float* emb    = (const float*)d_in[2];
    const float* Wih0   = (const float*)d_in[3];
    const float* Whh0   = (const float*)d_in[4];
    const float* bih0   = (const float*)d_in[5];
    const float* bhh0   = (const float*)d_in[6];
    const float* Wih1   = (const float*)d_in[7];
    const float* Whh1   = (const float*)d_in[8];
    const float* bih1   = (const float*)d_in[9];
    const float* bhh1   = (const float*)d_in[10];
    const float* Wout   = (const float*)d_in[11];
    const float* bout   = (const float*)d_in[12];

    float* out      = (float*)d_out;
    float* outprob  = out;
    float* rnnhid   = out + (size_t)M_ * V_;
    float* lastout  = rnnhid + 2 * B_ * H_;

    float *xw, *seq0, *seq1;
    cudaGetSymbolAddress((void**)&xw,   g_xw);
    cudaGetSymbolAddress((void**)&seq0, g_seq0);
    cudaGetSymbolAddress((void**)&seq1, g_seq1);

    const int scan_smem = (8 + 32) * WPAD * sizeof(float);   // ~164 KB
    cudaFuncSetAttribute(rnn_scan,
                         cudaFuncAttributeMaxDynamicSharedMemorySize, scan_smem);

    dim3 gproj(M_ / 128, H_ / 128);

    // Layer 0: xW = emb[ids] @ Wih0^T + bih0 (fused gather), then scan.
    sgemm_nt<<<gproj, 256>>>(nullptr, Wih0, bih0, xw, H_, E_, ids, emb);
    rnn_scan<<<NBLK, 256, scan_smem>>>(xw, Whh0, bhh0, hidden, seq0);

    // Layer 1.
    sgemm_nt<<<gproj, 256>>>(seq0, Wih1, bih1, xw, H_, H_, nullptr, nullptr);
    rnn_scan<<<NBLK, 256, scan_smem>>>(xw, Whh1, bhh1, hidden + B_ * H_, seq1);

    copy_hidden<<<(2 * B_ * H_) / 256, 256>>>(seq0, seq1, rnnhid);

    // Output projection: [4096,1024] x [32000,1024]^T
    dim3 gout(M_ / 128, V_ / 128);
    sgemm_nt<<<gout, 256>>>(seq1, Wout, bout, outprob, V_, H_, nullptr, nullptr);

    copy_last<<<(B_ * V_) / 256, 256>>>(outprob, lastout);
}

// round 5
// speedup vs baseline: 3.2916x; 1.6958x over previous
#include <cuda_runtime.h>
#include <cuda_bf16.h>
#include <math.h>
#include <stdint.h>

#define B_ 32
#define T_ 128
#define H_ 1024
#define E_ 1024
#define V_ 32000
#define M_ (B_*T_)   // 4096
#define NBLK 128
#define WPAD 1028

// ---- GEMM tiling (mma.sync bf16, Ampere-style pipeline) ----
#define BM 128
#define BN 128
#define BK 64                 // bf16 elements per chunk (128 B rows)
#define STAGES 4
#define CHUNKS 48             // 3 products x (1024/64)
#define STAGE_BYTES 32768     // A tile 16 KB + B tile 16 KB
#define SMEM_GEMM (STAGES * STAGE_BYTES)   // 128 KB

#define SW128(o) ((o) ^ (((o) >> 3) & 0x70))

// ------------------------- scratch (allocation-free) ------------------------
__device__ __align__(256) float g_xw[M_ * H_];
__device__ __align__(256) float g_seq0[M_ * H_];
__device__ __align__(256) float g_seq1[M_ * H_];
__device__ unsigned g_flags[NBLK];

__device__ __align__(256) __nv_bfloat16 g_Whi[(size_t)V_ * H_];
__device__ __align__(256) __nv_bfloat16 g_Wlo[(size_t)V_ * H_];
__device__ __align__(256) __nv_bfloat16 g_Wih0h[H_ * H_];
__device__ __align__(256) __nv_bfloat16 g_Wih0l[H_ * H_];
__device__ __align__(256) __nv_bfloat16 g_Wih1h[H_ * H_];
__device__ __align__(256) __nv_bfloat16 g_Wih1l[H_ * H_];
__device__ __align__(256) __nv_bfloat16 g_Xh[M_ * H_];
__device__ __align__(256) __nv_bfloat16 g_Xl[M_ * H_];

// ------------------------------ PTX helpers --------------------------------
__device__ __forceinline__ uint32_t smem_u32(const void* p) {
    uint32_t a;
    asm("{ .reg .u64 t; cvta.to.shared.u64 t, %1; cvt.u32.u64 %0, t; }"
        : "=r"(a) : "l"(p));
    return a;
}

__device__ __forceinline__ void cp_async16(uint32_t dst, const void* src) {
    asm volatile("cp.async.cg.shared.global [%0], [%1], 16;"
                 :: "r"(dst), "l"(src) : "memory");
}
__device__ __forceinline__ void cp_commit() {
    asm volatile("cp.async.commit_group;" ::: "memory");
}
__device__ __forceinline__ void cp_wait2() {
    asm volatile("cp.async.wait_group %0;" :: "n"(STAGES - 2) : "memory");
}

__device__ __forceinline__ void ldm4(uint32_t* r, uint32_t addr) {
    asm volatile("ldmatrix.sync.aligned.m8n8.x4.shared.b16 {%0,%1,%2,%3}, [%4];"
                 : "=r"(r[0]), "=r"(r[1]), "=r"(r[2]), "=r"(r[3]) : "r"(addr));
}

__device__ __forceinline__ void mma16816(float* d, const uint32_t* a,
                                         uint32_t b0, uint32_t b1) {
    asm volatile(
        "mma.sync.aligned.m16n8k16.row.col.f32.bf16.bf16.f32 "
        "{%0,%1,%2,%3}, {%4,%5,%6,%7}, {%8,%9}, {%0,%1,%2,%3};"
        : "+f"(d[0]), "+f"(d[1]), "+f"(d[2]), "+f"(d[3])
        : "r"(a[0]), "r"(a[1]), "r"(a[2]), "r"(a[3]), "r"(b0), "r"(b1));
}

__device__ __forceinline__ unsigned long long ffma2(
    unsigned long long a, unsigned long long b, unsigned long long c)
{
    unsigned long long d;
    asm("fma.rn.f32x2 %0, %1, %2, %3;" : "=l"(d) : "l"(a), "l"(b), "l"(c));
    return d;
}

// ---------------------------------------------------------------------------
// bf16-split (hi/lo) conversion kernels
// ---------------------------------------------------------------------------
__global__ void split2(const float4* __restrict__ src,
                       __nv_bfloat162* __restrict__ hi,
                       __nv_bfloat162* __restrict__ lo)
{
    int i = blockIdx.x * 256 + threadIdx.x;
    float4 v = src[i];
    __nv_bfloat16 hx = __float2bfloat16(v.x), hy = __float2bfloat16(v.y);
    __nv_bfloat16 hz = __float2bfloat16(v.z), hw = __float2bfloat16(v.w);
    __nv_bfloat16 lx = __float2bfloat16(v.x - __bfloat162float(hx));
    __nv_bfloat16 ly = __float2bfloat16(v.y - __bfloat162float(hy));
    __nv_bfloat16 lz = __float2bfloat16(v.z - __bfloat162float(hz));
    __nv_bfloat16 lw = __float2bfloat16(v.w - __bfloat162float(hw));
    hi[2*i]   = __halves2bfloat162(hx, hy);
    hi[2*i+1] = __halves2bfloat162(hz, hw);
    lo[2*i]   = __halves2bfloat162(lx, ly);
    lo[2*i+1] = __halves2bfloat162(lz, lw);
}

__global__ void split_gather(const int* __restrict__ ids,
                             const float* __restrict__ table,
                             __nv_bfloat162* __restrict__ hi,
                             __nv_bfloat162* __restrict__ lo)
{
    int i = blockIdx.x * 256 + threadIdx.x;     // over M_*H_/4 groups
    int m = i >> 8;                             // H_/4 = 256 groups/row
    int c = i & 255;
    float4 v = ((const float4*)(table + (size_t)ids[m] * H_))[c];
    __nv_bfloat16 hx = __float2bfloat16(v.x), hy = __float2bfloat16(v.y);
    __nv_bfloat16 hz = __float2bfloat16(v.z), hw = __float2bfloat16(v.w);
    __nv_bfloat16 lx = __float2bfloat16(v.x - __bfloat162float(hx));
    __nv_bfloat16 ly = __float2bfloat16(v.y - __bfloat162float(hy));
    __nv_bfloat16 lz = __float2bfloat16(v.z - __bfloat162float(hz));
    __nv_bfloat16 lw = __float2bfloat16(v.w - __bfloat162float(hw));
    hi[2*i]   = __halves2bfloat162(hx, hy);
    hi[2*i+1] = __halves2bfloat162(hz, hw);
    lo[2*i]   = __halves2bfloat162(lx, ly);
    lo[2*i+1] = __halves2bfloat162(lz, lw);
}

// ---------------------------------------------------------------------------
// bf16x3 GEMM via mma.sync (HMMA):
// C[m,n] = sum_k (Ah+Al)[m,k]*(Bh+Bl)[n,k] + bias[n]   (drop Al*Bl)
// K-schedule: 48 chunks of 64: p=0:(Ah,Bh) p=1:(Al,Bh) p=2:(Ah,Bl)
// 256 thr, warps 2(m) x 4(n), warp tile 64x32, cp.async 4-stage pipeline.
// ---------------------------------------------------------------------------
__global__ __launch_bounds__(256, 1) void gemm_bf16x3(
    const __nv_bfloat16* __restrict__ Ah, const __nv_bfloat16* __restrict__ Al,
    const __nv_bfloat16* __restrict__ Bh, const __nv_bfloat16* __restrict__ Bl,
    const float* __restrict__ bias, float* __restrict__ C, int Ntot)
{
    extern __shared__ __align__(1024) char sm[];
    const uint32_t sbase = smem_u32(sm);

    const int tid  = threadIdx.x;
    const int wid  = tid >> 5;
    const int lane = tid & 31;
    const int wm   = wid & 1;          // m half (64 rows)
    const int wn   = wid >> 1;         // n quarter (32 cols)
    const int m0   = blockIdx.x * BM;
    const int n0   = blockIdx.y * BN;

    const int lrow = tid >> 3;         // 0..31
    const int lc16 = (tid & 7) * 16;   // byte col within 128B row

    float acc[4][4][4];
    #pragma unroll
    for (int i = 0; i < 4; i++)
        #pragma unroll
        for (int j = 0; j < 4; j++)
            #pragma unroll
            for (int q = 0; q < 4; q++) acc[i][j][q] = 0.f;

    // ---- stage loader ----
    auto load_stage = [&](int c, int s) {
        const int p  = c >> 4;
        const int kk = (c & 15) * BK;
        const __nv_bfloat16* Ap = (p == 1) ? Al : Ah;
        const __nv_bfloat16* Bp = (p == 2) ? Bl : Bh;
        const uint32_t abase = sbase + s * STAGE_BYTES;
        const uint32_t bbase = abase + 16384;
        #pragma unroll
        for (int i = 0; i < 4; i++) {
            int r = lrow + i * 32;
            cp_async16(abase + SW128(r * 128 + lc16),
                       Ap + (size_t)(m0 + r) * H_ + kk + (lc16 >> 1));
        }
        #pragma unroll
        for (int i = 0; i < 4; i++) {
            int r = lrow + i * 32;
            cp_async16(bbase + SW128(r * 128 + lc16),
                       Bp + (size_t)(n0 + r) * H_ + kk + (lc16 >> 1));
        }
    };

    // prologue
    #pragma unroll
    for (int c = 0; c < STAGES - 1; c++) { load_stage(c, c); cp_commit(); }

    const int arow = wm * 64 + (lane & 15);            // A frag base row
    const int brow = wn * 32 + (lane & 15);            // B frag base row
    const int chalf = (lane >> 4) * 16;                // byte half-col

    for (int it = 0; it < CHUNKS; it++) {
        cp_wait2();
        __syncthreads();
        const int s = it & (STAGES - 1);
        const uint32_t abase = sbase + s * STAGE_BYTES;
        const uint32_t bbase = abase + 16384;

        #pragma unroll
        for (int k16 = 0; k16 < 4; k16++) {
            const int kb = k16 * 32 + chalf;
            uint32_t afr[4][4], bfr[2][4];
            #pragma unroll
            for (int mi = 0; mi < 4; mi++)
                ldm4(afr[mi], abase + SW128((arow + mi * 16) * 128 + kb));
            #pragma unroll
            for (int bj = 0; bj < 2; bj++)
                ldm4(bfr[bj], bbase + SW128((brow + bj * 16) * 128 + kb));
            #pragma unroll
            for (int mi = 0; mi < 4; mi++)
                #pragma unroll
                for (int nj = 0; nj < 4; nj++) {
                    const uint32_t* bq = bfr[nj >> 1];
                    mma16816(acc[mi][nj], afr[mi],
                             bq[nj & 1], bq[(nj & 1) + 2]);
                }
        }

        const int c = it + STAGES - 1;
        if (c < CHUNKS) load_stage(c, c & (STAGES - 1));
        cp_commit();
    }

    // ---- epilogue: direct global stores + bias ----
    const int erow = m0 + wm * 64 + (lane >> 2);
    const int ecol = n0 + wn * 32 + (lane & 3) * 2;
    #pragma unroll
    for (int mi = 0; mi < 4; mi++) {
        #pragma unroll
        for (int nj = 0; nj < 4; nj++) {
            int col = ecol + nj * 8;
            float b0 = bias[col], b1 = bias[col + 1];
            float2 v0 = make_float2(acc[mi][nj][0] + b0, acc[mi][nj][1] + b1);
            float2 v1 = make_float2(acc[mi][nj][2] + b0, acc[mi][nj][3] + b1);
            *(float2*)(C + (size_t)(erow + mi * 16) * Ntot + col) = v0;
            *(float2*)(C + (size_t)(erow + mi * 16 + 8) * Ntot + col) = v1;
        }
    }
}

// ---------------------------------------------------------------------------
// Persistent RNN scan (unchanged, proven)
// ---------------------------------------------------------------------------
__global__ __launch_bounds__(256, 1) void rnn_scan(
    const float* __restrict__ xw, const float* __restrict__ Whh,
    const float* __restrict__ bhh, const float* __restrict__ h0,
    float* __restrict__ seq)
{
    extern __shared__ float smem[];
    float* Ws = smem;
    float* sh = smem + 8 * WPAD;

    const int tid  = threadIdx.x;
    const int bid  = blockIdx.x;
    const int w    = tid >> 5;
    const int lane = tid & 31;
    const int bq   = lane >> 3;
    const int jloc = lane & 7;
    const int b    = w * 4 + bq;
    const int j    = bid * 8 + jloc;

    {
        const float4* W4 = (const float4*)(Whh + (size_t)bid * 8 * H_);
        #pragma unroll
        for (int i = 0; i < 8; i++) {
            int q = i * 256 + tid;
            int row = q >> 8, kv = q & 255;
            float4 v = W4[row * 256 + kv];
            *(float4*)(Ws + row * WPAD + kv * 4) = v;
        }
    }

    __shared__ unsigned sbase_f;
    if (tid == 0) sbase_f = g_flags[bid];
    __syncthreads();
    const unsigned base = sbase_f;
    const float bj = bhh[j];

    for (int t = 0; t < T_; t++) {
        if (t > 0) {
            if (tid < 32) {
                unsigned need = base + (unsigned)t;
                #pragma unroll
                for (int f = lane; f < NBLK; f += 32) {
                    while (*((volatile unsigned*)&g_flags[f]) < need) { }
                }
            }
            __syncthreads();
        }

        if (t == 0) {
            #pragma unroll
            for (int i = 0; i < 32; i++) {
                int q = i * 256 + tid;
                int bb = q >> 8, kv = q & 255;
                float4 v = __ldcg((const float4*)(h0 + (size_t)bb * H_) + kv);
                *(float4*)(sh + bb * WPAD + kv * 4) = v;
            }
        } else {
            #pragma unroll
            for (int i = 0; i < 32; i++) {
                int q = i * 256 + tid;
                int bb = q >> 8, kv = q & 255;
                float4 v = __ldcg(
                    (const float4*)(seq + ((size_t)bb * T_ + (t - 1)) * H_) + kv);
                *(float4*)(sh + bb * WPAD + kv * 4) = v;
            }
        }
        __syncthreads();

        const ulonglong2* h2 = (const ulonglong2*)(sh + b * WPAD);
        const ulonglong2* w2 = (const ulonglong2*)(Ws + jloc * WPAD);
        unsigned long long a0 = 0ull, a1 = 0ull, a2 = 0ull, a3 = 0ull;
        #pragma unroll 8
        for (int kk = 0; kk < 256; kk += 2) {
            ulonglong2 hv0 = h2[kk],     wv0 = w2[kk];
            ulonglong2 hv1 = h2[kk + 1], wv1 = w2[kk + 1];
            a0 = ffma2(hv0.x, wv0.x, a0);
            a1 = ffma2(hv0.y, wv0.y, a1);
            a2 = ffma2(hv1.x, wv1.x, a2);
            a3 = ffma2(hv1.y, wv1.y, a3);
        }
        float2 s0 = *(float2*)&a0, s1 = *(float2*)&a1;
        float2 s2 = *(float2*)&a2, s3 = *(float2*)&a3;
        float sum = ((s0.x + s0.y) + (s1.x + s1.y))
                  + ((s2.x + s2.y) + (s3.x + s3.y));

        float pre = sum + xw[((size_t)b * T_ + t) * H_ + j] + bj;
        seq[((size_t)b * T_ + t) * H_ + j] = tanhf(pre);

        __threadfence();
        __syncthreads();
        if (tid == 0) atomicExch(&g_flags[bid], base + (unsigned)t + 1u);
    }
}

__global__ void copy_hidden(const float* __restrict__ seq0,
                            const float* __restrict__ seq1,
                            float* __restrict__ out)
{
    int idx = blockIdx.x * 256 + threadIdx.x;
    int l = idx >> 15;
    int rem = idx & 32767;
    int b = rem >> 10, j = rem & 1023;
    const float* s = l ? seq1 : seq0;
    out[idx] = s[((size_t)b * T_ + (T_ - 1)) * H_ + j];
}

__global__ void copy_last(const float* __restrict__ outprob,
                          float* __restrict__ last)
{
    int idx = blockIdx.x * 256 + threadIdx.x;
    int b = idx / V_, v = idx - b * V_;
    last[idx] = outprob[((size_t)b * T_ + (T_ - 1)) * V_ + v];
}

// ---------------------------------------------------------------------------
extern "C" void kernel_launch(void* const* d_in, const int* in_sizes, int n_in,
                              void* d_out, int out_size)
{
    const int*   ids    = (const int*)  d_in[0];
    const float* hidden = (const float*)d_in[1];
    const float* emb    = (const float*)d_in[2];
    const float* Wih0   = (const float*)d_in[3];
    const float* Whh0   = (const float*)d_in[4];
    const float* bih0   = (const float*)d_in[5];
    const float* bhh0   = (const float*)d_in[6];
    const float* Wih1   = (const float*)d_in[7];
    const float* Whh1   = (const float*)d_in[8];
    const float* bih1   = (const float*)d_in[9];
    const float* bhh1   = (const float*)d_in[10];
    const float* Wout   = (const float*)d_in[11];
    const float* bout   = (const float*)d_in[12];

    float* out      = (float*)d_out;
    float* outprob  = out;
    float* rnnhid   = out + (size_t)M_ * V_;
    float* lastout  = rnnhid + 2 * B_ * H_;

    float *xw, *seq0, *seq1;
    cudaGetSymbolAddress((void**)&xw,   g_xw);
    cudaGetSymbolAddress((void**)&seq0, g_seq0);
    cudaGetSymbolAddress((void**)&seq1, g_seq1);
    __nv_bfloat16 *Whi, *Wlo, *W0h, *W0l, *W1h, *W1l, *Xh, *Xl;
    cudaGetSymbolAddress((void**)&Whi, g_Whi);
    cudaGetSymbolAddress((void**)&Wlo, g_Wlo);
    cudaGetSymbolAddress((void**)&W0h, g_Wih0h);
    cudaGetSymbolAddress((void**)&W0l, g_Wih0l);
    cudaGetSymbolAddress((void**)&W1h, g_Wih1h);
    cudaGetSymbolAddress((void**)&W1l, g_Wih1l);
    cudaGetSymbolAddress((void**)&Xh, g_Xh);
    cudaGetSymbolAddress((void**)&Xl, g_Xl);

    const int scan_smem = (8 + 32) * WPAD * sizeof(float);
    cudaFuncSetAttribute(rnn_scan,
                         cudaFuncAttributeMaxDynamicSharedMemorySize, scan_smem);
    cudaFuncSetAttribute(gemm_bf16x3,
                         cudaFuncAttributeMaxDynamicSharedMemorySize, SMEM_GEMM);

    // weight splits (recomputed each call: deterministic)
    split2<<<(V_*H_/4)/256, 256>>>((const float4*)Wout,
                                   (__nv_bfloat162*)Whi, (__nv_bfloat162*)Wlo);
    split2<<<(H_*H_/4)/256, 256>>>((const float4*)Wih0,
                                   (__nv_bfloat162*)W0h, (__nv_bfloat162*)W0l);
    split2<<<(H_*H_/4)/256, 256>>>((const float4*)Wih1,
                                   (__nv_bfloat162*)W1h, (__nv_bfloat162*)W1l);

    // ---- layer 0 ----
    split_gather<<<(M_*H_/4)/256, 256>>>(ids, emb,
                                         (__nv_bfloat162*)Xh, (__nv_bfloat162*)Xl);
    gemm_bf16x3<<<dim3(M_/BM, H_/BN), 256, SMEM_GEMM>>>(
        Xh, Xl, W0h, W0l, bih0, xw, H_);
    rnn_scan<<<NBLK, 256, scan_smem>>>(xw, Whh0, bhh0, hidden, seq0);

    // ---- layer 1 ----
    split2<<<(M_*H_/4)/256, 256>>>((const float4*)seq0,
                                   (__nv_bfloat162*)Xh, (__nv_bfloat162*)Xl);
    gemm_bf16x3<<<dim3(M_/BM, H_/BN), 256, SMEM_GEMM>>>(
        Xh, Xl, W1h, W1l, bih1, xw, H_);
    rnn_scan<<<NBLK, 256, scan_smem>>>(xw, Whh1, bhh1, hidden + B_ * H_, seq1);

    copy_hidden<<<(2 * B_ * H_) / 256, 256>>>(seq0, seq1, rnnhid);

    // ---- output projection: [4096,1024] x [32000,1024]^T ----
    split2<<<(M_*H_/4)/256, 256>>>((const float4*)seq1,
                                   (__nv_bfloat162*)Xh, (__nv_bfloat162*)Xl);
    gemm_bf16x3<<<dim3(M_/BM, V_/BN), 256, SMEM_GEMM>>>(
        Xh, Xl, Whi, Wlo, bout, outprob, V_);

    copy_last<<<(B_ * V_) / 256, 256>>>(outprob, lastout);
}

// round 7
// speedup vs baseline: 3.9413x; 1.1974x over previous
#include <cuda_runtime.h>
#include <cuda_fp16.h>
#include <math.h>
#include <stdint.h>

#define B_ 32
#define T_ 128
#define H_ 1024
#define E_ 1024
#define V_ 32000
#define M_ (B_*T_)   // 4096
#define NBLK 128
#define WPAD 1028

// ---- GEMM tiling (mma.sync fp16 2-term, Ampere-style pipeline) ----
#define BM 128
#define BN 128
#define BK 64                 // fp16 elements per chunk (128 B rows)
#define STAGES 4
#define KC 16                 // 1024 / 64
#define STAGE_BYTES 49152     // Ah 16K + Al 16K + B 16K
#define SMEM_GEMM (STAGES * STAGE_BYTES)   // 192 KB

#define LO_SCALE 2048.0f
#define LO_INV   (1.0f/2048.0f)

#define SW128(o) ((o) ^ (((o) >> 3) & 0x70))

// ------------------------- scratch (allocation-free) ------------------------
__device__ __align__(256) float g_xw[M_ * H_];
__device__ __align__(256) float g_seq0[M_ * H_];
__device__ __align__(256) float g_seq1[M_ * H_];
__device__ unsigned g_flags[NBLK];

__device__ __align__(256) __half g_Wout_h[(size_t)V_ * H_];
__device__ __align__(256) __half g_Wih0_h[H_ * H_];
__device__ __align__(256) __half g_Wih1_h[H_ * H_];
__device__ __align__(256) __half g_Xh[M_ * H_];
__device__ __align__(256) __half g_Xl[M_ * H_];

// ------------------------------ PTX helpers --------------------------------
__device__ __forceinline__ uint32_t smem_u32(const void* p) {
    uint32_t a;
    asm("{ .reg .u64 t; cvta.to.shared.u64 t, %1; cvt.u32.u64 %0, t; }"
        : "=r"(a) : "l"(p));
    return a;
}

__device__ __forceinline__ void cp_async16(uint32_t dst, const void* src) {
    asm volatile("cp.async.cg.shared.global [%0], [%1], 16;"
                 :: "r"(dst), "l"(src) : "memory");
}
__device__ __forceinline__ void cp_commit() {
    asm volatile("cp.async.commit_group;" ::: "memory");
}
__device__ __forceinline__ void cp_wait2() {
    asm volatile("cp.async.wait_group %0;" :: "n"(STAGES - 2) : "memory");
}

__device__ __forceinline__ void ldm4(uint32_t* r, uint32_t addr) {
    asm volatile("ldmatrix.sync.aligned.m8n8.x4.shared.b16 {%0,%1,%2,%3}, [%4];"
                 : "=r"(r[0]), "=r"(r[1]), "=r"(r[2]), "=r"(r[3]) : "r"(addr));
}

__device__ __forceinline__ void mma16816(float* d, const uint32_t* a,
                                         uint32_t b0, uint32_t b1) {
    asm volatile(
        "mma.sync.aligned.m16n8k16.row.col.f32.f16.f16.f32 "
        "{%0,%1,%2,%3}, {%4,%5,%6,%7}, {%8,%9}, {%0,%1,%2,%3};"
        : "+f"(d[0]), "+f"(d[1]), "+f"(d[2]), "+f"(d[3])
        : "r"(a[0]), "r"(a[1]), "r"(a[2]), "r"(a[3]), "r"(b0), "r"(b1));
}

__device__ __forceinline__ unsigned long long ffma2(
    unsigned long long a, unsigned long long b, unsigned long long c)
{
    unsigned long long d;
    asm("fma.rn.f32x2 %0, %1, %2, %3;" : "=l"(d) : "l"(a), "l"(b), "l"(c));
    return d;
}

// ---------------------------------------------------------------------------
// conversion kernels
// ---------------------------------------------------------------------------
// plain fp32 -> fp16 (weights)
__global__ void conv_half(const float4* __restrict__ src,
                          __half2* __restrict__ dst)
{
    int i = blockIdx.x * 256 + threadIdx.x;
    float4 v = src[i];
    dst[2*i]   = __floats2half2_rn(v.x, v.y);
    dst[2*i+1] = __floats2half2_rn(v.z, v.w);
}

// fp32 -> (hi fp16, scaled-lo fp16) for activations
__global__ void split_half(const float4* __restrict__ src,
                           __half2* __restrict__ hi, __half2* __restrict__ lo)
{
    int i = blockIdx.x * 256 + threadIdx.x;
    float4 v = src[i];
    __half hx = __float2half_rn(v.x), hy = __float2half_rn(v.y);
    __half hz = __float2half_rn(v.z), hw = __float2half_rn(v.w);
    float lx = (v.x - __half2float(hx)) * LO_SCALE;
    float ly = (v.y - __half2float(hy)) * LO_SCALE;
    float lz = (v.z - __half2float(hz)) * LO_SCALE;
    float lw = (v.w - __half2float(hw)) * LO_SCALE;
    hi[2*i]   = __halves2half2(hx, hy);
    hi[2*i+1] = __halves2half2(hz, hw);
    lo[2*i]   = __floats2half2_rn(lx, ly);
    lo[2*i+1] = __floats2half2_rn(lz, lw);
}

// gathered: X[m,:] = emb[ids[m], :]
__global__ void split_gather_half(const int* __restrict__ ids,
                                  const float* __restrict__ table,
                                  __half2* __restrict__ hi,
                                  __half2* __restrict__ lo)
{
    int i = blockIdx.x * 256 + threadIdx.x;     // M_*H_/4 groups
    int m = i >> 8;
    int c = i & 255;
    float4 v = ((const float4*)(table + (size_t)ids[m] * H_))[c];
    __half hx = __float2half_rn(v.x), hy = __float2half_rn(v.y);
    __half hz = __float2half_rn(v.z), hw = __float2half_rn(v.w);
    float lx = (v.x - __half2float(hx)) * LO_SCALE;
    float ly = (v.y - __half2float(hy)) * LO_SCALE;
    float lz = (v.z - __half2float(hz)) * LO_SCALE;
    float lw = (v.w - __half2float(hw)) * LO_SCALE;
    hi[2*i]   = __halves2half2(hx, hy);
    hi[2*i+1] = __halves2half2(hz, hw);
    lo[2*i]   = __floats2half2_rn(lx, ly);
    lo[2*i+1] = __floats2half2_rn(lz, lw);
}

// ---------------------------------------------------------------------------
// fp16x2 GEMM via mma.sync (HMMA):
// C[m,n] = Ah[m,:]·B[n,:] + (1/2048)·Al[m,:]·B[n,:] + bias[n]
// 16 K-chunks of 64; per chunk one B stage shared by hi and lo products.
// 256 thr, warps 2(m) x 4(n), warp tile 64x32, cp.async 4-stage pipeline.
// ---------------------------------------------------------------------------
__global__ __launch_bounds__(256, 1) void gemm_fp16x2(
    const __half* __restrict__ Ah, const __half* __restrict__ Al,
    const __half* __restrict__ Bw,
    const float* __restrict__ bias, float* __restrict__ C, int Ntot)
{
    extern __shared__ __align__(1024) char sm[];
    const uint32_t sbase = smem_u32(sm);

    const int tid  = threadIdx.x;
    const int wid  = tid >> 5;
    const int lane = tid & 31;
    const int wm   = wid & 1;          // m half (64 rows)
    const int wn   = wid >> 1;         // n quarter (32 cols)
    const int m0   = blockIdx.x * BM;
    const int n0   = blockIdx.y * BN;

    const int lrow = tid >> 3;         // 0..31
    const int lc16 = (tid & 7) * 16;   // byte col within 128B row

    float acch[4][4][4];
    float accl[4][4][4];
    #pragma unroll
    for (int i = 0; i < 4; i++)
        #pragma unroll
        for (int j = 0; j < 4; j++)
            #pragma unroll
            for (int q = 0; q < 4; q++) { acch[i][j][q] = 0.f; accl[i][j][q] = 0.f; }

    // ---- stage loader: Ah(16K) + Al(16K) + B(16K) ----
    auto load_stage = [&](int kc, int s) {
        const int kk = kc * BK;
        const uint32_t ah_b = sbase + s * STAGE_BYTES;
        const uint32_t al_b = ah_b + 16384;
        const uint32_t b_b  = ah_b + 32768;
        #pragma unroll
        for (int i = 0; i < 4; i++) {
            int r = lrow + i * 32;
            uint32_t so = SW128(r * 128 + lc16);
            cp_async16(ah_b + so, Ah + (size_t)(m0 + r) * H_ + kk + (lc16 >> 1));
            cp_async16(al_b + so, Al + (size_t)(m0 + r) * H_ + kk + (lc16 >> 1));
            cp_async16(b_b  + so, Bw + (size_t)(n0 + r) * H_ + kk + (lc16 >> 1));
        }
    };

    // prologue
    #pragma unroll
    for (int c = 0; c < STAGES - 1; c++) { load_stage(c, c); cp_commit(); }

    const int arow  = wm * 64 + (lane & 15);           // A frag base row
    const int brow  = wn * 32 + (lane & 15);           // B frag base row
    const int chalf = (lane >> 4) * 16;                // byte half-col

    for (int it = 0; it < KC; it++) {
        cp_wait2();
        __syncthreads();
        const int s = it & (STAGES - 1);
        const uint32_t ah_b = sbase + s * STAGE_BYTES;
        const uint32_t al_b = ah_b + 16384;
        const uint32_t b_b  = ah_b + 32768;

        #pragma unroll
        for (int k16 = 0; k16 < 4; k16++) {
            const int kb = k16 * 32 + chalf;
            uint32_t bfr[2][4];
            #pragma unroll
            for (int bj = 0; bj < 2; bj++)
                ldm4(bfr[bj], b_b + SW128((brow + bj * 16) * 128 + kb));

            uint32_t afh[4][4], afl[4][4];
            #pragma unroll
            for (int mi = 0; mi < 4; mi++) {
                uint32_t ro = SW128((arow + mi * 16) * 128 + kb);
                ldm4(afh[mi], ah_b + ro);
                ldm4(afl[mi], al_b + ro);
            }
            #pragma unroll
            for (int mi = 0; mi < 4; mi++)
                #pragma unroll
                for (int nj = 0; nj < 4; nj++) {
                    const uint32_t* bq = bfr[nj >> 1];
                    uint32_t b0 = bq[nj & 1], b1 = bq[(nj & 1) + 2];
                    mma16816(acch[mi][nj], afh[mi], b0, b1);
                    mma16816(accl[mi][nj], afl[mi], b0, b1);
                }
        }

        const int c = it + STAGES - 1;
        if (c < KC) load_stage(c, c & (STAGES - 1));
        cp_commit();
    }

    // ---- epilogue: combine hi + lo/2048, add bias, store ----
    const int erow = m0 + wm * 64 + (lane >> 2);
    const int ecol = n0 + wn * 32 + (lane & 3) * 2;
    #pragma unroll
    for (int mi = 0; mi < 4; mi++) {
        #pragma unroll
        for (int nj = 0; nj < 4; nj++) {
            int col = ecol + nj * 8;
            float b0 = bias[col], b1 = bias[col + 1];
            float2 v0, v1;
            v0.x = acch[mi][nj][0] + accl[mi][nj][0] * LO_INV + b0;
            v0.y = acch[mi][nj][1] + accl[mi][nj][1] * LO_INV + b1;
            v1.x = acch[mi][nj][2] + accl[mi][nj][2] * LO_INV + b0;
            v1.y = acch[mi][nj][3] + accl[mi][nj][3] * LO_INV + b1;
            *(float2*)(C + (size_t)(erow + mi * 16) * Ntot + col) = v0;
            *(float2*)(C + (size_t)(erow + mi * 16 + 8) * Ntot + col) = v1;
        }
    }
}

// ---------------------------------------------------------------------------
// Persistent RNN scan (unchanged, proven)
// ---------------------------------------------------------------------------
__global__ __launch_bounds__(256, 1) void rnn_scan(
    const float* __restrict__ xw, const float* __restrict__ Whh,
    const float* __restrict__ bhh, const float* __restrict__ h0,
    float* __restrict__ seq)
{
    extern __shared__ float smem[];
    float* Ws = smem;
    float* sh = smem + 8 * WPAD;

    const int tid  = threadIdx.x;
    const int bid  = blockIdx.x;
    const int w    = tid >> 5;
    const int lane = tid & 31;
    const int bq   = lane >> 3;
    const int jloc = lane & 7;
    const int b    = w * 4 + bq;
    const int j    = bid * 8 + jloc;

    {
        const float4* W4 = (const float4*)(Whh + (size_t)bid * 8 * H_);
        #pragma unroll
        for (int i = 0; i < 8; i++) {
            int q = i * 256 + tid;
            int row = q >> 8, kv = q & 255;
            float4 v = W4[row * 256 + kv];
            *(float4*)(Ws + row * WPAD + kv * 4) = v;
        }
    }

    __shared__ unsigned sbase_f;
    if (tid == 0) sbase_f = g_flags[bid];
    __syncthreads();
    const unsigned base = sbase_f;
    const float bj = bhh[j];

    for (int t = 0; t < T_; t++) {
        if (t > 0) {
            if (tid < 32) {
                unsigned need = base + (unsigned)t;
                #pragma unroll
                for (int f = lane; f < NBLK; f += 32) {
                    while (*((volatile unsigned*)&g_flags[f]) < need) { }
                }
            }
            __syncthreads();
        }

        if (t == 0) {
            #pragma unroll
            for (int i = 0; i < 32; i++) {
                int q = i * 256 + tid;
                int bb = q >> 8, kv = q & 255;
                float4 v = __ldcg((const float4*)(h0 + (size_t)bb * H_) + kv);
                *(float4*)(sh + bb * WPAD + kv * 4) = v;
            }
        } else {
            #pragma unroll
            for (int i = 0; i < 32; i++) {
                int q = i * 256 + tid;
                int bb = q >> 8, kv = q & 255;
                float4 v = __ldcg(
                    (const float4*)(seq + ((size_t)bb * T_ + (t - 1)) * H_) + kv);
                *(float4*)(sh + bb * WPAD + kv * 4) = v;
            }
        }
        __syncthreads();

        const ulonglong2* h2 = (const ulonglong2*)(sh + b * WPAD);
        const ulonglong2* w2 = (const ulonglong2*)(Ws + jloc * WPAD);
        unsigned long long a0 = 0ull, a1 = 0ull, a2 = 0ull, a3 = 0ull;
        #pragma unroll 8
        for (int kk = 0; kk < 256; kk += 2) {
            ulonglong2 hv0 = h2[kk],     wv0 = w2[kk];
            ulonglong2 hv1 = h2[kk + 1], wv1 = w2[kk + 1];
            a0 = ffma2(hv0.x, wv0.x, a0);
            a1 = ffma2(hv0.y, wv0.y, a1);
            a2 = ffma2(hv1.x, wv1.x, a2);
            a3 = ffma2(hv1.y, wv1.y, a3);
        }
        float2 s0 = *(float2*)&a0, s1 = *(float2*)&a1;
        float2 s2 = *(float2*)&a2, s3 = *(float2*)&a3;
        float sum = ((s0.x + s0.y) + (s1.x + s1.y))
                  + ((s2.x + s2.y) + (s3.x + s3.y));

        float pre = sum + xw[((size_t)b * T_ + t) * H_ + j] + bj;
        seq[((size_t)b * T_ + t) * H_ + j] = tanhf(pre);

        __threadfence();
        __syncthreads();
        if (tid == 0) atomicExch(&g_flags[bid], base + (unsigned)t + 1u);
    }
}

__global__ void copy_hidden(const float* __restrict__ seq0,
                            const float* __restrict__ seq1,
                            float* __restrict__ out)
{
    int idx = blockIdx.x * 256 + threadIdx.x;
    int l = idx >> 15;
    int rem = idx & 32767;
    int b = rem >> 10, j = rem & 1023;
    const float* s = l ? seq1 : seq0;
    out[idx] = s[((size_t)b * T_ + (T_ - 1)) * H_ + j];
}

__global__ void copy_last(const float* __restrict__ outprob,
                          float* __restrict__ last)
{
    int idx = blockIdx.x * 256 + threadIdx.x;
    int b = idx / V_, v = idx - b * V_;
    last[idx] = outprob[((size_t)b * T_ + (T_ - 1)) * V_ + v];
}

// ---------------------------------------------------------------------------
extern "C" void kernel_launch(void* const* d_in, const int* in_sizes, int n_in,
                              void* d_out, int out_size)
{
    const int*   ids    = (const int*)  d_in[0];
    const float* hidden = (const float*)d_in[1];
    const float* emb    = (const float*)d_in[2];
    const float* Wih0   = (const float*)d_in[3];
    const float* Whh0   = (const float*)d_in[4];
    const float* bih0   = (const float*)d_in[5];
    const float* bhh0   = (const float*)d_in[6];
    const float* Wih1   = (const float*)d_in[7];
    const float* Whh1   = (const float*)d_in[8];
    const float* bih1   = (const float*)d_in[9];
    const float* bhh1   = (const float*)d_in[10];
    const float* Wout   = (const float*)d_in[11];
    const float* bout   = (const float*)d_in[12];

    float* out      = (float*)d_out;
    float* outprob  = out;
    float* rnnhid   = out + (size_t)M_ * V_;
    float* lastout  = rnnhid + 2 * B_ * H_;

    float *xw, *seq0, *seq1;
    cudaGetSymbolAddress((void**)&xw,   g_xw);
    cudaGetSymbolAddress((void**)&seq0, g_seq0);
    cudaGetSymbolAddress((void**)&seq1, g_seq1);
    __half *Wo_h, *W0_h, *W1_h, *Xh, *Xl;
    cudaGetSymbolAddress((void**)&Wo_h, g_Wout_h);
    cudaGetSymbolAddress((void**)&W0_h, g_Wih0_h);
    cudaGetSymbolAddress((void**)&W1_h, g_Wih1_h);
    cudaGetSymbolAddress((void**)&Xh, g_Xh);
    cudaGetSymbolAddress((void**)&Xl, g_Xl);

    const int scan_smem = (8 + 32) * WPAD * sizeof(float);
    cudaFuncSetAttribute(rnn_scan,
                         cudaFuncAttributeMaxDynamicSharedMemorySize, scan_smem);
    cudaFuncSetAttribute(gemm_fp16x2,
                         cudaFuncAttributeMaxDynamicSharedMemorySize, SMEM_GEMM);

    // weight conversions (recomputed each call: deterministic)
    conv_half<<<(V_*H_/4)/256, 256>>>((const float4*)Wout, (__half2*)Wo_h);
    conv_half<<<(H_*H_/4)/256, 256>>>((const float4*)Wih0, (__half2*)W0_h);
    conv_half<<<(H_*H_/4)/256, 256>>>((const float4*)Wih1, (__half2*)W1_h);

    // ---- layer 0 ----
    split_gather_half<<<(M_*H_/4)/256, 256>>>(ids, emb,
                                              (__half2*)Xh, (__half2*)Xl);
    gemm_fp16x2<<<dim3(M_/BM, H_/BN), 256, SMEM_GEMM>>>(
        Xh, Xl, W0_h, bih0, xw, H_);
    rnn_scan<<<NBLK, 256, scan_smem>>>(xw, Whh0, bhh0, hidden, seq0);

    // ---- layer 1 ----
    split_half<<<(M_*H_/4)/256, 256>>>((const float4*)seq0,
                                       (__half2*)Xh, (__half2*)Xl);
    gemm_fp16x2<<<dim3(M_/BM, H_/BN), 256, SMEM_GEMM>>>(
        Xh, Xl, W1_h, bih1, xw, H_);
    rnn_scan<<<NBLK, 256, scan_smem>>>(xw, Whh1, bhh1, hidden + B_ * H_, seq1);

    copy_hidden<<<(2 * B_ * H_) / 256, 256>>>(seq0, seq1, rnnhid);

    // ---- output projection: [4096,1024] x [32000,1024]^T ----
    split_half<<<(M_*H_/4)/256, 256>>>((const float4*)seq1,
                                       (__half2*)Xh, (__half2*)Xl);
    gemm_fp16x2<<<dim3(M_/BM, V_/BN), 256, SMEM_GEMM>>>(
        Xh, Xl, Wo_h, bout, outprob, V_);

    copy_last<<<(B_ * V_) / 256, 256>>>(outprob, lastout);
}

// round 8
// speedup vs baseline: 4.8264x; 1.2246x over previous
#include <cuda_runtime.h>
#include <cuda_fp16.h>
#include <math.h>
#include <stdint.h>

#define B_ 32
#define T_ 128
#define H_ 1024
#define E_ 1024
#define V_ 32000
#define M_ (B_*T_)   // 4096
#define NBLK 128
#define WPAD 1028
#define PSTRIDE 260   // partial-buffer warp stride (floats), bank-staggered

// ---- GEMM tiling (mma.sync fp16 2-term, Ampere-style pipeline) ----
#define BM 128
#define BN 128
#define BK 64                 // fp16 elements per chunk (128 B rows)
#define STAGES 4
#define KC 16                 // 1024 / 64
#define STAGE_BYTES 49152     // Ah 16K + Al 16K + B 16K
#define SMEM_GEMM (STAGES * STAGE_BYTES)   // 192 KB

#define LO_SCALE 2048.0f
#define LO_INV   (1.0f/2048.0f)

#define SW128(o) ((o) ^ (((o) >> 3) & 0x70))

// ------------------------- scratch (allocation-free) ------------------------
__device__ __align__(256) float g_xw[M_ * H_];
__device__ __align__(256) float g_seq0[M_ * H_];
__device__ __align__(256) float g_seq1[M_ * H_];
__device__ unsigned g_flags[NBLK];

__device__ __align__(256) __half g_Wout_h[(size_t)V_ * H_];
__device__ __align__(256) __half g_Wih0_h[H_ * H_];
__device__ __align__(256) __half g_Wih1_h[H_ * H_];
__device__ __align__(256) __half g_Xh[M_ * H_];
__device__ __align__(256) __half g_Xl[M_ * H_];

// ------------------------------ PTX helpers --------------------------------
__device__ __forceinline__ uint32_t smem_u32(const void* p) {
    uint32_t a;
    asm("{ .reg .u64 t; cvta.to.shared.u64 t, %1; cvt.u32.u64 %0, t; }"
        : "=r"(a) : "l"(p));
    return a;
}

__device__ __forceinline__ void cp_async16(uint32_t dst, const void* src) {
    asm volatile("cp.async.cg.shared.global [%0], [%1], 16;"
                 :: "r"(dst), "l"(src) : "memory");
}
__device__ __forceinline__ void cp_commit() {
    asm volatile("cp.async.commit_group;" ::: "memory");
}
__device__ __forceinline__ void cp_wait2() {
    asm volatile("cp.async.wait_group %0;" :: "n"(STAGES - 2) : "memory");
}

__device__ __forceinline__ void ldm4(uint32_t* r, uint32_t addr) {
    asm volatile("ldmatrix.sync.aligned.m8n8.x4.shared.b16 {%0,%1,%2,%3}, [%4];"
                 : "=r"(r[0]), "=r"(r[1]), "=r"(r[2]), "=r"(r[3]) : "r"(addr));
}

__device__ __forceinline__ void mma16816(float* d, const uint32_t* a,
                                         uint32_t b0, uint32_t b1) {
    asm volatile(
        "mma.sync.aligned.m16n8k16.row.col.f32.f16.f16.f32 "
        "{%0,%1,%2,%3}, {%4,%5,%6,%7}, {%8,%9}, {%0,%1,%2,%3};"
        : "+f"(d[0]), "+f"(d[1]), "+f"(d[2]), "+f"(d[3])
        : "r"(a[0]), "r"(a[1]), "r"(a[2]), "r"(a[3]), "r"(b0), "r"(b1));
}

__device__ __forceinline__ unsigned long long ffma2(
    unsigned long long a, unsigned long long b, unsigned long long c)
{
    unsigned long long d;
    asm("fma.rn.f32x2 %0, %1, %2, %3;" : "=l"(d) : "l"(a), "l"(b), "l"(c));
    return d;
}

// ---------------------------------------------------------------------------
// conversion kernels
// ---------------------------------------------------------------------------
__global__ void conv_half(const float4* __restrict__ src,
                          __half2* __restrict__ dst)
{
    int i = blockIdx.x * 256 + threadIdx.x;
    float4 v = src[i];
    dst[2*i]   = __floats2half2_rn(v.x, v.y);
    dst[2*i+1] = __floats2half2_rn(v.z, v.w);
}

__global__ void split_half(const float4* __restrict__ src,
                           __half2* __restrict__ hi, __half2* __restrict__ lo)
{
    int i = blockIdx.x * 256 + threadIdx.x;
    float4 v = src[i];
    __half hx = __float2half_rn(v.x), hy = __float2half_rn(v.y);
    __half hz = __float2half_rn(v.z), hw = __float2half_rn(v.w);
    float lx = (v.x - __half2float(hx)) * LO_SCALE;
    float ly = (v.y - __half2float(hy)) * LO_SCALE;
    float lz = (v.z - __half2float(hz)) * LO_SCALE;
    float lw = (v.w - __half2float(hw)) * LO_SCALE;
    hi[2*i]   = __halves2half2(hx, hy);
    hi[2*i+1] = __halves2half2(hz, hw);
    lo[2*i]   = __floats2half2_rn(lx, ly);
    lo[2*i+1] = __floats2half2_rn(lz, lw);
}

__global__ void split_gather_half(const int* __restrict__ ids,
                                  const float* __restrict__ table,
                                  __half2* __restrict__ hi,
                                  __half2* __restrict__ lo)
{
    int i = blockIdx.x * 256 + threadIdx.x;     // M_*H_/4 groups
    int m = i >> 8;
    int c = i & 255;
    float4 v = ((const float4*)(table + (size_t)ids[m] * H_))[c];
    __half hx = __float2half_rn(v.x), hy = __float2half_rn(v.y);
    __half hz = __float2half_rn(v.z), hw = __float2half_rn(v.w);
    float lx = (v.x - __half2float(hx)) * LO_SCALE;
    float ly = (v.y - __half2float(hy)) * LO_SCALE;
    float lz = (v.z - __half2float(hz)) * LO_SCALE;
    float lw = (v.w - __half2float(hw)) * LO_SCALE;
    hi[2*i]   = __halves2half2(hx, hy);
    hi[2*i+1] = __halves2half2(hz, hw);
    lo[2*i]   = __floats2half2_rn(lx, ly);
    lo[2*i+1] = __floats2half2_rn(lz, lw);
}

// ---------------------------------------------------------------------------
// fp16x2 GEMM via mma.sync (HMMA) — unchanged from round 7 (proven)
// ---------------------------------------------------------------------------
__global__ __launch_bounds__(256, 1) void gemm_fp16x2(
    const __half* __restrict__ Ah, const __half* __restrict__ Al,
    const __half* __restrict__ Bw,
    const float* __restrict__ bias, float* __restrict__ C, int Ntot)
{
    extern __shared__ __align__(1024) char sm[];
    const uint32_t sbase = smem_u32(sm);

    const int tid  = threadIdx.x;
    const int wid  = tid >> 5;
    const int lane = tid & 31;
    const int wm   = wid & 1;
    const int wn   = wid >> 1;
    const int m0   = blockIdx.x * BM;
    const int n0   = blockIdx.y * BN;

    const int lrow = tid >> 3;
    const int lc16 = (tid & 7) * 16;

    float acch[4][4][4];
    float accl[4][4][4];
    #pragma unroll
    for (int i = 0; i < 4; i++)
        #pragma unroll
        for (int j = 0; j < 4; j++)
            #pragma unroll
            for (int q = 0; q < 4; q++) { acch[i][j][q] = 0.f; accl[i][j][q] = 0.f; }

    auto load_stage = [&](int kc, int s) {
        const int kk = kc * BK;
        const uint32_t ah_b = sbase + s * STAGE_BYTES;
        const uint32_t al_b = ah_b + 16384;
        const uint32_t b_b  = ah_b + 32768;
        #pragma unroll
        for (int i = 0; i < 4; i++) {
            int r = lrow + i * 32;
            uint32_t so = SW128(r * 128 + lc16);
            cp_async16(ah_b + so, Ah + (size_t)(m0 + r) * H_ + kk + (lc16 >> 1));
            cp_async16(al_b + so, Al + (size_t)(m0 + r) * H_ + kk + (lc16 >> 1));
            cp_async16(b_b  + so, Bw + (size_t)(n0 + r) * H_ + kk + (lc16 >> 1));
        }
    };

    #pragma unroll
    for (int c = 0; c < STAGES - 1; c++) { load_stage(c, c); cp_commit(); }

    const int arow  = wm * 64 + (lane & 15);
    const int brow  = wn * 32 + (lane & 15);
    const int chalf = (lane >> 4) * 16;

    for (int it = 0; it < KC; it++) {
        cp_wait2();
        __syncthreads();
        const int s = it & (STAGES - 1);
        const uint32_t ah_b = sbase + s * STAGE_BYTES;
        const uint32_t al_b = ah_b + 16384;
        const uint32_t b_b  = ah_b + 32768;

        #pragma unroll
        for (int k16 = 0; k16 < 4; k16++) {
            const int kb = k16 * 32 + chalf;
            uint32_t bfr[2][4];
            #pragma unroll
            for (int bj = 0; bj < 2; bj++)
                ldm4(bfr[bj], b_b + SW128((brow + bj * 16) * 128 + kb));

            uint32_t afh[4][4], afl[4][4];
            #pragma unroll
            for (int mi = 0; mi < 4; mi++) {
                uint32_t ro = SW128((arow + mi * 16) * 128 + kb);
                ldm4(afh[mi], ah_b + ro);
                ldm4(afl[mi], al_b + ro);
            }
            #pragma unroll
            for (int mi = 0; mi < 4; mi++)
                #pragma unroll
                for (int nj = 0; nj < 4; nj++) {
                    const uint32_t* bq = bfr[nj >> 1];
                    uint32_t b0 = bq[nj & 1], b1 = bq[(nj & 1) + 2];
                    mma16816(acch[mi][nj], afh[mi], b0, b1);
                    mma16816(accl[mi][nj], afl[mi], b0, b1);
                }
        }

        const int c = it + STAGES - 1;
        if (c < KC) load_stage(c, c & (STAGES - 1));
        cp_commit();
    }

    const int erow = m0 + wm * 64 + (lane >> 2);
    const int ecol = n0 + wn * 32 + (lane & 3) * 2;
    #pragma unroll
    for (int mi = 0; mi < 4; mi++) {
        #pragma unroll
        for (int nj = 0; nj < 4; nj++) {
            int col = ecol + nj * 8;
            float b0 = bias[col], b1 = bias[col + 1];
            float2 v0, v1;
            v0.x = acch[mi][nj][0] + accl[mi][nj][0] * LO_INV + b0;
            v0.y = acch[mi][nj][1] + accl[mi][nj][1] * LO_INV + b1;
            v1.x = acch[mi][nj][2] + accl[mi][nj][2] * LO_INV + b0;
            v1.y = acch[mi][nj][3] + accl[mi][nj][3] * LO_INV + b1;
            *(float2*)(C + (size_t)(erow + mi * 16) * Ntot + col) = v0;
            *(float2*)(C + (size_t)(erow + mi * 16 + 8) * Ntot + col) = v1;
        }
    }
}

// ---------------------------------------------------------------------------
// Persistent RNN scan v2: warp-split-K with smem-broadcast W reads.
// CTA bid owns j in [bid*8, bid*8+8). Warp w owns k-slice [w*128,(w+1)*128).
// Lane = b. Each lane computes partials for all 8 j (W reads are warp-uniform
// broadcasts; h row read once, reused across j). Cross-warp reduce via smem.
// LDS traffic per CTA-step: ~160 KB (vs 2 MB in v1).
// ---------------------------------------------------------------------------
__global__ __launch_bounds__(256, 1) void rnn_scan(
    const float* __restrict__ xw, const float* __restrict__ Whh,
    const float* __restrict__ bhh, const float* __restrict__ h0,
    float* __restrict__ seq)
{
    extern __shared__ float smem[];
    float* Ws   = smem;                        // [8][WPAD]
    float* sh   = smem + 8 * WPAD;             // [32][WPAD]
    float* part = smem + 40 * WPAD;            // [8][PSTRIDE]

    const int tid  = threadIdx.x;
    const int bid  = blockIdx.x;
    const int w    = tid >> 5;
    const int lane = tid & 31;

    // Cache this CTA's 8 W_hh rows in smem (once).
    {
        const float4* W4 = (const float4*)(Whh + (size_t)bid * 8 * H_);
        #pragma unroll
        for (int i = 0; i < 8; i++) {
            int q = i * 256 + tid;
            int row = q >> 8, kv = q & 255;
            float4 v = W4[row * 256 + kv];
            *(float4*)(Ws + row * WPAD + kv * 4) = v;
        }
    }

    __shared__ unsigned sbase_f;
    if (tid == 0) sbase_f = g_flags[bid];
    __syncthreads();
    const unsigned base = sbase_f;

    const int rb = tid & 31;        // reduction: b index
    const int rj = tid >> 5;        // reduction: j local index
    const int jglob = bid * 8 + rj;
    const float bj = bhh[jglob];

    const int ks = w * 128;         // this warp's k-slice start

    for (int t = 0; t < T_; t++) {
        // --- wait for all CTAs to have finished step t-1 ---
        if (t > 0) {
            if (tid < 32) {
                unsigned need = base + (unsigned)t;
                #pragma unroll
                for (int f = lane; f < NBLK; f += 32) {
                    while (*((volatile unsigned*)&g_flags[f]) < need) { }
                }
            }
            __syncthreads();
        }

        // --- stage h_{t-1} (32 x 1024) into smem ---
        if (t == 0) {
            #pragma unroll
            for (int i = 0; i < 32; i++) {
                int q = i * 256 + tid;
                int bb = q >> 8, kv = q & 255;
                float4 v = __ldcg((const float4*)(h0 + (size_t)bb * H_) + kv);
                *(float4*)(sh + bb * WPAD + kv * 4) = v;
            }
        } else {
            #pragma unroll
            for (int i = 0; i < 32; i++) {
                int q = i * 256 + tid;
                int bb = q >> 8, kv = q & 255;
                float4 v = __ldcg(
                    (const float4*)(seq + ((size_t)bb * T_ + (t - 1)) * H_) + kv);
                *(float4*)(sh + bb * WPAD + kv * 4) = v;
            }
        }
        __syncthreads();

        // --- partials: lane=b, this warp's 128-wide k-slice, all 8 j ---
        {
            const ulonglong2* h2 = (const ulonglong2*)(sh + lane * WPAD + ks);
            unsigned long long a0[8], a1[8];
            #pragma unroll
            for (int j = 0; j < 8; j++) { a0[j] = 0ull; a1[j] = 0ull; }
            #pragma unroll 4
            for (int k4 = 0; k4 < 32; k4++) {        // 32 x 16B = 128 floats
                ulonglong2 hv = h2[k4];
                #pragma unroll
                for (int j = 0; j < 8; j++) {
                    ulonglong2 wv =
                        ((const ulonglong2*)(Ws + j * WPAD + ks))[k4];
                    a0[j] = ffma2(hv.x, wv.x, a0[j]);
                    a1[j] = ffma2(hv.y, wv.y, a1[j]);
                }
            }
            #pragma unroll
            for (int j = 0; j < 8; j++) {
                float2 s0 = *(float2*)&a0[j];
                float2 s1 = *(float2*)&a1[j];
                part[w * PSTRIDE + j * 32 + lane] =
                    (s0.x + s0.y) + (s1.x + s1.y);
            }
        }
        __syncthreads();

        // --- reduce across warps: thread (rj, rb) sums 8 partials ---
        {
            float s = 0.f;
            #pragma unroll
            for (int ww = 0; ww < 8; ww++)
                s += part[ww * PSTRIDE + rj * 32 + rb];
            float pre = s + xw[((size_t)rb * T_ + t) * H_ + jglob] + bj;
            seq[((size_t)rb * T_ + t) * H_ + jglob] = tanhf(pre);
        }

        // --- publish step t ---
        __threadfence();
        __syncthreads();
        if (tid == 0) atomicExch(&g_flags[bid], base + (unsigned)t + 1u);
    }
}

__global__ void copy_hidden(const float* __restrict__ seq0,
                            const float* __restrict__ seq1,
                            float* __restrict__ out)
{
    int idx = blockIdx.x * 256 + threadIdx.x;
    int l = idx >> 15;
    int rem = idx & 32767;
    int b = rem >> 10, j = rem & 1023;
    const float* s = l ? seq1 : seq0;
    out[idx] = s[((size_t)b * T_ + (T_ - 1)) * H_ + j];
}

__global__ void copy_last(const float* __restrict__ outprob,
                          float* __restrict__ last)
{
    int idx = blockIdx.x * 256 + threadIdx.x;
    int b = idx / V_, v = idx - b * V_;
    last[idx] = outprob[((size_t)b * T_ + (T_ - 1)) * V_ + v];
}

// ---------------------------------------------------------------------------
extern "C" void kernel_launch(void* const* d_in, const int* in_sizes, int n_in,
                              void* d_out, int out_size)
{
    const int*   ids    = (const int*)  d_in[0];
    const float* hidden = (const float*)d_in[1];
    const float* emb    = (const float*)d_in[2];
    const float* Wih0   = (const float*)d_in[3];
    const float* Whh0   = (const float*)d_in[4];
    const float* bih0   = (const float*)d_in[5];
    const float* bhh0   = (const float*)d_in[6];
    const float* Wih1   = (const float*)d_in[7];
    const float* Whh1   = (const float*)d_in[8];
    const float* bih1   = (const float*)d_in[9];
    const float* bhh1   = (const float*)d_in[10];
    const float* Wout   = (const float*)d_in[11];
    const float* bout   = (const float*)d_in[12];

    float* out      = (float*)d_out;
    float* outprob  = out;
    float* rnnhid   = out + (size_t)M_ * V_;
    float* lastout  = rnnhid + 2 * B_ * H_;

    float *xw, *seq0, *seq1;
    cudaGetSymbolAddress((void**)&xw,   g_xw);
    cudaGetSymbolAddress((void**)&seq0, g_seq0);
    cudaGetSymbolAddress((void**)&seq1, g_seq1);
    __half *Wo_h, *W0_h, *W1_h, *Xh, *Xl;
    cudaGetSymbolAddress((void**)&Wo_h, g_Wout_h);
    cudaGetSymbolAddress((void**)&W0_h, g_Wih0_h);
    cudaGetSymbolAddress((void**)&W1_h, g_Wih1_h);
    cudaGetSymbolAddress((void**)&Xh, g_Xh);
    cudaGetSymbolAddress((void**)&Xl, g_Xl);

    const int scan_smem = (40 * WPAD + 8 * PSTRIDE) * sizeof(float); // ~173 KB
    cudaFuncSetAttribute(rnn_scan,
                         cudaFuncAttributeMaxDynamicSharedMemorySize, scan_smem);
    cudaFuncSetAttribute(gemm_fp16x2,
                         cudaFuncAttributeMaxDynamicSharedMemorySize, SMEM_GEMM);

    // weight conversions (recomputed each call: deterministic)
    conv_half<<<(V_*H_/4)/256, 256>>>((const float4*)Wout, (__half2*)Wo_h);
    conv_half<<<(H_*H_/4)/256, 256>>>((const float4*)Wih0, (__half2*)W0_h);
    conv_half<<<(H_*H_/4)/256, 256>>>((const float4*)Wih1, (__half2*)W1_h);

    // ---- layer 0 ----
    split_gather_half<<<(M_*H_/4)/256, 256>>>(ids, emb,
                                              (__half2*)Xh, (__half2*)Xl);
    gemm_fp16x2<<<dim3(M_/BM, H_/BN), 256, SMEM_GEMM>>>(
        Xh, Xl, W0_h, bih0, xw, H_);
    rnn_scan<<<NBLK, 256, scan_smem>>>(xw, Whh0, bhh0, hidden, seq0);

    // ---- layer 1 ----
    split_half<<<(M_*H_/4)/256, 256>>>((const float4*)seq0,
                                       (__half2*)Xh, (__half2*)Xl);
    gemm_fp16x2<<<dim3(M_/BM, H_/BN), 256, SMEM_GEMM>>>(
        Xh, Xl, W1_h, bih1, xw, H_);
    rnn_scan<<<NBLK, 256, scan_smem>>>(xw, Whh1, bhh1, hidden + B_ * H_, seq1);

    copy_hidden<<<(2 * B_ * H_) / 256, 256>>>(seq0, seq1, rnnhid);

    // ---- output projection: [4096,1024] x [32000,1024]^T ----
    split_half<<<(M_*H_/4)/256, 256>>>((const float4*)seq1,
                                       (__half2*)Xh, (__half2*)Xl);
    gemm_fp16x2<<<dim3(M_/BM, V_/BN), 256, SMEM_GEMM>>>(
        Xh, Xl, Wo_h, bout, outprob, V_);

    copy_last<<<(B_ * V_) / 256, 256>>>(outprob, lastout);
}

// round 9
// speedup vs baseline: 6.0344x; 1.2503x over previous
#include <cuda_runtime.h>
#include <cuda_fp16.h>
#include <math.h>
#include <stdint.h>

#define B_ 32
#define T_ 128
#define H_ 1024
#define E_ 1024
#define V_ 32000
#define M_ (B_*T_)   // 4096
#define NBLK 128
#define WPAD 1028
#define PSTRIDE 260

// ---- GEMM tiling ----
#define BM 128
#define BN 128
#define BK 64
#define STAGES 4
#define KC 16
#define STAGE2_BYTES 49152    // 2-term: Ah + Al + B
#define SMEM_GEMM2 (STAGES * STAGE2_BYTES)   // 192 KB
#define STAGE1_BYTES 32768    // 1-term: Ah + B
#define SMEM_GEMM1 (STAGES * STAGE1_BYTES)   // 128 KB

#define LO_SCALE 2048.0f
#define LO_INV   (1.0f/2048.0f)

#define SW128(o) ((o) ^ (((o) >> 3) & 0x70))

// ------------------------- scratch (allocation-free) ------------------------
__device__ __align__(256) float g_xw[M_ * H_];
__device__ __align__(256) float g_seq0[M_ * H_];
__device__ __align__(256) float g_seq1[M_ * H_];
__device__ unsigned g_flags[NBLK];

__device__ __align__(256) __half g_Wout_h[(size_t)V_ * H_];
__device__ __align__(256) __half g_Wih0_h[H_ * H_];
__device__ __align__(256) __half g_Wih1_h[H_ * H_];
__device__ __align__(256) __half g_Xh[M_ * H_];
__device__ __align__(256) __half g_Xl[M_ * H_];

// ------------------------------ PTX helpers --------------------------------
__device__ __forceinline__ uint32_t smem_u32(const void* p) {
    uint32_t a;
    asm("{ .reg .u64 t; cvta.to.shared.u64 t, %1; cvt.u32.u64 %0, t; }"
        : "=r"(a) : "l"(p));
    return a;
}

__device__ __forceinline__ void cp_async16(uint32_t dst, const void* src) {
    asm volatile("cp.async.cg.shared.global [%0], [%1], 16;"
                 :: "r"(dst), "l"(src) : "memory");
}
__device__ __forceinline__ void cp_commit() {
    asm volatile("cp.async.commit_group;" ::: "memory");
}
__device__ __forceinline__ void cp_wait2() {
    asm volatile("cp.async.wait_group %0;" :: "n"(STAGES - 2) : "memory");
}

__device__ __forceinline__ void ldm4(uint32_t* r, uint32_t addr) {
    asm volatile("ldmatrix.sync.aligned.m8n8.x4.shared.b16 {%0,%1,%2,%3}, [%4];"
                 : "=r"(r[0]), "=r"(r[1]), "=r"(r[2]), "=r"(r[3]) : "r"(addr));
}

__device__ __forceinline__ void mma16816(float* d, const uint32_t* a,
                                         uint32_t b0, uint32_t b1) {
    asm volatile(
        "mma.sync.aligned.m16n8k16.row.col.f32.f16.f16.f32 "
        "{%0,%1,%2,%3}, {%4,%5,%6,%7}, {%8,%9}, {%0,%1,%2,%3};"
        : "+f"(d[0]), "+f"(d[1]), "+f"(d[2]), "+f"(d[3])
        : "r"(a[0]), "r"(a[1]), "r"(a[2]), "r"(a[3]), "r"(b0), "r"(b1));
}

__device__ __forceinline__ unsigned long long ffma2(
    unsigned long long a, unsigned long long b, unsigned long long c)
{
    unsigned long long d;
    asm("fma.rn.f32x2 %0, %1, %2, %3;" : "=l"(d) : "l"(a), "l"(b), "l"(c));
    return d;
}

// ---------------------------------------------------------------------------
// conversion kernels
// ---------------------------------------------------------------------------
__global__ void conv_half(const float4* __restrict__ src,
                          __half2* __restrict__ dst)
{
    int i = blockIdx.x * 256 + threadIdx.x;
    float4 v = src[i];
    dst[2*i]   = __floats2half2_rn(v.x, v.y);
    dst[2*i+1] = __floats2half2_rn(v.z, v.w);
}

__global__ void split_half(const float4* __restrict__ src,
                           __half2* __restrict__ hi, __half2* __restrict__ lo)
{
    int i = blockIdx.x * 256 + threadIdx.x;
    float4 v = src[i];
    __half hx = __float2half_rn(v.x), hy = __float2half_rn(v.y);
    __half hz = __float2half_rn(v.z), hw = __float2half_rn(v.w);
    float lx = (v.x - __half2float(hx)) * LO_SCALE;
    float ly = (v.y - __half2float(hy)) * LO_SCALE;
    float lz = (v.z - __half2float(hz)) * LO_SCALE;
    float lw = (v.w - __half2float(hw)) * LO_SCALE;
    hi[2*i]   = __halves2half2(hx, hy);
    hi[2*i+1] = __halves2half2(hz, hw);
    lo[2*i]   = __floats2half2_rn(lx, ly);
    lo[2*i+1] = __floats2half2_rn(lz, lw);
}

__global__ void split_gather_half(const int* __restrict__ ids,
                                  const float* __restrict__ table,
                                  __half2* __restrict__ hi,
                                  __half2* __restrict__ lo)
{
    int i = blockIdx.x * 256 + threadIdx.x;
    int m = i >> 8;
    int c = i & 255;
    float4 v = ((const float4*)(table + (size_t)ids[m] * H_))[c];
    __half hx = __float2half_rn(v.x), hy = __float2half_rn(v.y);
    __half hz = __float2half_rn(v.z), hw = __float2half_rn(v.w);
    float lx = (v.x - __half2float(hx)) * LO_SCALE;
    float ly = (v.y - __half2float(hy)) * LO_SCALE;
    float lz = (v.z - __half2float(hz)) * LO_SCALE;
    float lw = (v.w - __half2float(hw)) * LO_SCALE;
    hi[2*i]   = __halves2half2(hx, hy);
    hi[2*i+1] = __halves2half2(hz, hw);
    lo[2*i]   = __floats2half2_rn(lx, ly);
    lo[2*i+1] = __floats2half2_rn(lz, lw);
}

// ---------------------------------------------------------------------------
// 2-term fp16 GEMM (input projections) — proven, unchanged
// ---------------------------------------------------------------------------
__global__ __launch_bounds__(256, 1) void gemm_fp16x2(
    const __half* __restrict__ Ah, const __half* __restrict__ Al,
    const __half* __restrict__ Bw,
    const float* __restrict__ bias, float* __restrict__ C, int Ntot)
{
    extern __shared__ __align__(1024) char sm[];
    const uint32_t sbase = smem_u32(sm);

    const int tid  = threadIdx.x;
    const int wid  = tid >> 5;
    const int lane = tid & 31;
    const int wm   = wid & 1;
    const int wn   = wid >> 1;
    const int m0   = blockIdx.x * BM;
    const int n0   = blockIdx.y * BN;

    const int lrow = tid >> 3;
    const int lc16 = (tid & 7) * 16;

    float acch[4][4][4];
    float accl[4][4][4];
    #pragma unroll
    for (int i = 0; i < 4; i++)
        #pragma unroll
        for (int j = 0; j < 4; j++)
            #pragma unroll
            for (int q = 0; q < 4; q++) { acch[i][j][q] = 0.f; accl[i][j][q] = 0.f; }

    auto load_stage = [&](int kc, int s) {
        const int kk = kc * BK;
        const uint32_t ah_b = sbase + s * STAGE2_BYTES;
        const uint32_t al_b = ah_b + 16384;
        const uint32_t b_b  = ah_b + 32768;
        #pragma unroll
        for (int i = 0; i < 4; i++) {
            int r = lrow + i * 32;
            uint32_t so = SW128(r * 128 + lc16);
            cp_async16(ah_b + so, Ah + (size_t)(m0 + r) * H_ + kk + (lc16 >> 1));
            cp_async16(al_b + so, Al + (size_t)(m0 + r) * H_ + kk + (lc16 >> 1));
            cp_async16(b_b  + so, Bw + (size_t)(n0 + r) * H_ + kk + (lc16 >> 1));
        }
    };

    #pragma unroll
    for (int c = 0; c < STAGES - 1; c++) { load_stage(c, c); cp_commit(); }

    const int arow  = wm * 64 + (lane & 15);
    const int brow  = wn * 32 + (lane & 15);
    const int chalf = (lane >> 4) * 16;

    for (int it = 0; it < KC; it++) {
        cp_wait2();
        __syncthreads();
        const int s = it & (STAGES - 1);
        const uint32_t ah_b = sbase + s * STAGE2_BYTES;
        const uint32_t al_b = ah_b + 16384;
        const uint32_t b_b  = ah_b + 32768;

        #pragma unroll
        for (int k16 = 0; k16 < 4; k16++) {
            const int kb = k16 * 32 + chalf;
            uint32_t bfr[2][4];
            #pragma unroll
            for (int bj = 0; bj < 2; bj++)
                ldm4(bfr[bj], b_b + SW128((brow + bj * 16) * 128 + kb));

            uint32_t afh[4][4], afl[4][4];
            #pragma unroll
            for (int mi = 0; mi < 4; mi++) {
                uint32_t ro = SW128((arow + mi * 16) * 128 + kb);
                ldm4(afh[mi], ah_b + ro);
                ldm4(afl[mi], al_b + ro);
            }
            #pragma unroll
            for (int mi = 0; mi < 4; mi++)
                #pragma unroll
                for (int nj = 0; nj < 4; nj++) {
                    const uint32_t* bq = bfr[nj >> 1];
                    uint32_t b0 = bq[nj & 1], b1 = bq[(nj & 1) + 2];
                    mma16816(acch[mi][nj], afh[mi], b0, b1);
                    mma16816(accl[mi][nj], afl[mi], b0, b1);
                }
        }

        const int c = it + STAGES - 1;
        if (c < KC) load_stage(c, c & (STAGES - 1));
        cp_commit();
    }

    const int erow = m0 + wm * 64 + (lane >> 2);
    const int ecol = n0 + wn * 32 + (lane & 3) * 2;
    #pragma unroll
    for (int mi = 0; mi < 4; mi++) {
        #pragma unroll
        for (int nj = 0; nj < 4; nj++) {
            int col = ecol + nj * 8;
            float b0 = bias[col], b1 = bias[col + 1];
            float2 v0, v1;
            v0.x = acch[mi][nj][0] + accl[mi][nj][0] * LO_INV + b0;
            v0.y = acch[mi][nj][1] + accl[mi][nj][1] * LO_INV + b1;
            v1.x = acch[mi][nj][2] + accl[mi][nj][2] * LO_INV + b0;
            v1.y = acch[mi][nj][3] + accl[mi][nj][3] * LO_INV + b1;
            *(float2*)(C + (size_t)(erow + mi * 16) * Ntot + col) = v0;
            *(float2*)(C + (size_t)(erow + mi * 16 + 8) * Ntot + col) = v1;
        }
    }
}

// ---------------------------------------------------------------------------
// 1-term fp16 GEMM (output projection): C = A·B^T + bias. Half the MMAs.
// ---------------------------------------------------------------------------
__global__ __launch_bounds__(256, 1) void gemm_fp16x1(
    const __half* __restrict__ Ah, const __half* __restrict__ Bw,
    const float* __restrict__ bias, float* __restrict__ C, int Ntot)
{
    extern __shared__ __align__(1024) char sm[];
    const uint32_t sbase = smem_u32(sm);

    const int tid  = threadIdx.x;
    const int wid  = tid >> 5;
    const int lane = tid & 31;
    const int wm   = wid & 1;
    const int wn   = wid >> 1;
    const int m0   = blockIdx.x * BM;
    const int n0   = blockIdx.y * BN;

    const int lrow = tid >> 3;
    const int lc16 = (tid & 7) * 16;

    float acch[4][4][4];
    #pragma unroll
    for (int i = 0; i < 4; i++)
        #pragma unroll
        for (int j = 0; j < 4; j++)
            #pragma unroll
            for (int q = 0; q < 4; q++) acch[i][j][q] = 0.f;

    auto load_stage = [&](int kc, int s) {
        const int kk = kc * BK;
        const uint32_t ah_b = sbase + s * STAGE1_BYTES;
        const uint32_t b_b  = ah_b + 16384;
        #pragma unroll
        for (int i = 0; i < 4; i++) {
            int r = lrow + i * 32;
            uint32_t so = SW128(r * 128 + lc16);
            cp_async16(ah_b + so, Ah + (size_t)(m0 + r) * H_ + kk + (lc16 >> 1));
            cp_async16(b_b  + so, Bw + (size_t)(n0 + r) * H_ + kk + (lc16 >> 1));
        }
    };

    #pragma unroll
    for (int c = 0; c < STAGES - 1; c++) { load_stage(c, c); cp_commit(); }

    const int arow  = wm * 64 + (lane & 15);
    const int brow  = wn * 32 + (lane & 15);
    const int chalf = (lane >> 4) * 16;

    for (int it = 0; it < KC; it++) {
        cp_wait2();
        __syncthreads();
        const int s = it & (STAGES - 1);
        const uint32_t ah_b = sbase + s * STAGE1_BYTES;
        const uint32_t b_b  = ah_b + 16384;

        #pragma unroll
        for (int k16 = 0; k16 < 4; k16++) {
            const int kb = k16 * 32 + chalf;
            uint32_t bfr[2][4];
            #pragma unroll
            for (int bj = 0; bj < 2; bj++)
                ldm4(bfr[bj], b_b + SW128((brow + bj * 16) * 128 + kb));

            uint32_t afh[4][4];
            #pragma unroll
            for (int mi = 0; mi < 4; mi++)
                ldm4(afh[mi], ah_b + SW128((arow + mi * 16) * 128 + kb));

            #pragma unroll
            for (int mi = 0; mi < 4; mi++)
                #pragma unroll
                for (int nj = 0; nj < 4; nj++) {
                    const uint32_t* bq = bfr[nj >> 1];
                    mma16816(acch[mi][nj], afh[mi],
                             bq[nj & 1], bq[(nj & 1) + 2]);
                }
        }

        const int c = it + STAGES - 1;
        if (c < KC) load_stage(c, c & (STAGES - 1));
        cp_commit();
    }

    const int erow = m0 + wm * 64 + (lane >> 2);
    const int ecol = n0 + wn * 32 + (lane & 3) * 2;
    #pragma unroll
    for (int mi = 0; mi < 4; mi++) {
        #pragma unroll
        for (int nj = 0; nj < 4; nj++) {
            int col = ecol + nj * 8;
            float b0 = bias[col], b1 = bias[col + 1];
            float2 v0, v1;
            v0.x = acch[mi][nj][0] + b0;
            v0.y = acch[mi][nj][1] + b1;
            v1.x = acch[mi][nj][2] + b0;
            v1.y = acch[mi][nj][3] + b1;
            *(float2*)(C + (size_t)(erow + mi * 16) * Ntot + col) = v0;
            *(float2*)(C + (size_t)(erow + mi * 16 + 8) * Ntot + col) = v1;
        }
    }
}

// ---------------------------------------------------------------------------
// Persistent RNN scan v2 (unchanged from round 8, proven)
// ---------------------------------------------------------------------------
__global__ __launch_bounds__(256, 1) void rnn_scan(
    const float* __restrict__ xw, const float* __restrict__ Whh,
    const float* __restrict__ bhh, const float* __restrict__ h0,
    float* __restrict__ seq)
{
    extern __shared__ float smem[];
    float* Ws   = smem;
    float* sh   = smem + 8 * WPAD;
    float* part = smem + 40 * WPAD;

    const int tid  = threadIdx.x;
    const int bid  = blockIdx.x;
    const int w    = tid >> 5;
    const int lane = tid & 31;

    {
        const float4* W4 = (const float4*)(Whh + (size_t)bid * 8 * H_);
        #pragma unroll
        for (int i = 0; i < 8; i++) {
            int q = i * 256 + tid;
            int row = q >> 8, kv = q & 255;
            float4 v = W4[row * 256 + kv];
            *(float4*)(Ws + row * WPAD + kv * 4) = v;
        }
    }

    __shared__ unsigned sbase_f;
    if (tid == 0) sbase_f = g_flags[bid];
    __syncthreads();
    const unsigned base = sbase_f;

    const int rb = tid & 31;
    const int rj = tid >> 5;
    const int jglob = bid * 8 + rj;
    const float bj = bhh[jglob];

    const int ks = w * 128;

    for (int t = 0; t < T_; t++) {
        if (t > 0) {
            if (tid < 32) {
                unsigned need = base + (unsigned)t;
                #pragma unroll
                for (int f = lane; f < NBLK; f += 32) {
                    while (*((volatile unsigned*)&g_flags[f]) < need) { }
                }
            }
            __syncthreads();
        }

        if (t == 0) {
            #pragma unroll
            for (int i = 0; i < 32; i++) {
                int q = i * 256 + tid;
                int bb = q >> 8, kv = q & 255;
                float4 v = __ldcg((const float4*)(h0 + (size_t)bb * H_) + kv);
                *(float4*)(sh + bb * WPAD + kv * 4) = v;
            }
        } else {
            #pragma unroll
            for (int i = 0; i < 32; i++) {
                int q = i * 256 + tid;
                int bb = q >> 8, kv = q & 255;
                float4 v = __ldcg(
                    (const float4*)(seq + ((size_t)bb * T_ + (t - 1)) * H_) + kv);
                *(float4*)(sh + bb * WPAD + kv * 4) = v;
            }
        }
        __syncthreads();

        {
            const ulonglong2* h2 = (const ulonglong2*)(sh + lane * WPAD + ks);
            unsigned long long a0[8], a1[8];
            #pragma unroll
            for (int j = 0; j < 8; j++) { a0[j] = 0ull; a1[j] = 0ull; }
            #pragma unroll 4
            for (int k4 = 0; k4 < 32; k4++) {
                ulonglong2 hv = h2[k4];
                #pragma unroll
                for (int j = 0; j < 8; j++) {
                    ulonglong2 wv =
                        ((const ulonglong2*)(Ws + j * WPAD + ks))[k4];
                    a0[j] = ffma2(hv.x, wv.x, a0[j]);
                    a1[j] = ffma2(hv.y, wv.y, a1[j]);
                }
            }
            #pragma unroll
            for (int j = 0; j < 8; j++) {
                float2 s0 = *(float2*)&a0[j];
                float2 s1 = *(float2*)&a1[j];
                part[w * PSTRIDE + j * 32 + lane] =
                    (s0.x + s0.y) + (s1.x + s1.y);
            }
        }
        __syncthreads();

        {
            float s = 0.f;
            #pragma unroll
            for (int ww = 0; ww < 8; ww++)
                s += part[ww * PSTRIDE + rj * 32 + rb];
            float pre = s + xw[((size_t)rb * T_ + t) * H_ + jglob] + bj;
            seq[((size_t)rb * T_ + t) * H_ + jglob] = tanhf(pre);
        }

        __threadfence();
        __syncthreads();
        if (tid == 0) atomicExch(&g_flags[bid], base + (unsigned)t + 1u);
    }
}

__global__ void copy_hidden(const float* __restrict__ seq0,
                            const float* __restrict__ seq1,
                            float* __restrict__ out)
{
    int idx = blockIdx.x * 256 + threadIdx.x;
    int l = idx >> 15;
    int rem = idx & 32767;
    int b = rem >> 10, j = rem & 1023;
    const float* s = l ? seq1 : seq0;
    out[idx] = s[((size_t)b * T_ + (T_ - 1)) * H_ + j];
}

__global__ void copy_last(const float* __restrict__ outprob,
                          float* __restrict__ last)
{
    int idx = blockIdx.x * 256 + threadIdx.x;
    int b = idx / V_, v = idx - b * V_;
    last[idx] = outprob[((size_t)b * T_ + (T_ - 1)) * V_ + v];
}

// ---------------------------------------------------------------------------
extern "C" void kernel_launch(void* const* d_in, const int* in_sizes, int n_in,
                              void* d_out, int out_size)
{
    const int*   ids    = (const int*)  d_in[0];
    const float* hidden = (const float*)d_in[1];
    const float* emb    = (const float*)d_in[2];
    const float* Wih0   = (const float*)d_in[3];
    const float* Whh0   = (const float*)d_in[4];
    const float* bih0   = (const float*)d_in[5];
    const float* bhh0   = (const float*)d_in[6];
    const float* Wih1   = (const float*)d_in[7];
    const float* Whh1   = (const float*)d_in[8];
    const float* bih1   = (const float*)d_in[9];
    const float* bhh1   = (const float*)d_in[10];
    const float* Wout   = (const float*)d_in[11];
    const float* bout   = (const float*)d_in[12];

    float* out      = (float*)d_out;
    float* outprob  = out;
    float* rnnhid   = out + (size_t)M_ * V_;
    float* lastout  = rnnhid + 2 * B_ * H_;

    float *xw, *seq0, *seq1;
    cudaGetSymbolAddress((void**)&xw,   g_xw);
    cudaGetSymbolAddress((void**)&seq0, g_seq0);
    cudaGetSymbolAddress((void**)&seq1, g_seq1);
    __half *Wo_h, *W0_h, *W1_h, *Xh, *Xl;
    cudaGetSymbolAddress((void**)&Wo_h, g_Wout_h);
    cudaGetSymbolAddress((void**)&W0_h, g_Wih0_h);
    cudaGetSymbolAddress((void**)&W1_h, g_Wih1_h);
    cudaGetSymbolAddress((void**)&Xh, g_Xh);
    cudaGetSymbolAddress((void**)&Xl, g_Xl);

    const int scan_smem = (40 * WPAD + 8 * PSTRIDE) * sizeof(float);
    cudaFuncSetAttribute(rnn_scan,
                         cudaFuncAttributeMaxDynamicSharedMemorySize, scan_smem);
    cudaFuncSetAttribute(gemm_fp16x2,
                         cudaFuncAttributeMaxDynamicSharedMemorySize, SMEM_GEMM2);
    cudaFuncSetAttribute(gemm_fp16x1,
                         cudaFuncAttributeMaxDynamicSharedMemorySize, SMEM_GEMM1);

    // weight conversions (recomputed each call: deterministic)
    conv_half<<<(V_*H_/4)/256, 256>>>((const float4*)Wout, (__half2*)Wo_h);
    conv_half<<<(H_*H_/4)/256, 256>>>((const float4*)Wih0, (__half2*)W0_h);
    conv_half<<<(H_*H_/4)/256, 256>>>((const float4*)Wih1, (__half2*)W1_h);

    // ---- layer 0 ----
    split_gather_half<<<(M_*H_/4)/256, 256>>>(ids, emb,
                                              (__half2*)Xh, (__half2*)Xl);
    gemm_fp16x2<<<dim3(M_/BM, H_/BN), 256, SMEM_GEMM2>>>(
        Xh, Xl, W0_h, bih0, xw, H_);
    rnn_scan<<<NBLK, 256, scan_smem>>>(xw, Whh0, bhh0, hidden, seq0);

    // ---- layer 1 ----
    split_half<<<(M_*H_/4)/256, 256>>>((const float4*)seq0,
                                       (__half2*)Xh, (__half2*)Xl);
    gemm_fp16x2<<<dim3(M_/BM, H_/BN), 256, SMEM_GEMM2>>>(
        Xh, Xl, W1_h, bih1, xw, H_);
    rnn_scan<<<NBLK, 256, scan_smem>>>(xw, Whh1, bhh1, hidden + B_ * H_, seq1);

    copy_hidden<<<(2 * B_ * H_) / 256, 256>>>(seq0, seq1, rnnhid);

    // ---- output projection: single fp16 product ----
    conv_half<<<(M_*H_/4)/256, 256>>>((const float4*)seq1, (__half2*)Xh);
    gemm_fp16x1<<<dim3(M_/BM, V_/BN), 256, SMEM_GEMM1>>>(
        Xh, Wo_h, bout, outprob, V_);

    copy_last<<<(B_ * V_) / 256, 256>>>(outprob, lastout);
}